// round 8
// baseline (speedup 1.0000x reference)
#include <cuda_runtime.h>
#include <cuda_bf16.h>
#include <cuda_fp16.h>
#include <cstdint>

// Problem dims
#define BB 1024
#define TT 512
#define DD 128
#define HH 256
#define CCLS 2
#define NROWS 16
#define NCTA (BB / NROWS)   // 64 CTAs
#define NTHR 512

// ---- fragment-packed fp16 weights (device global; no allocations allowed) ----
// Gates [0, 262144) u32, coalesced layout:
//   i = ((((w*32 + s)*4 + q)*32 + t)*4 + e),  u = q*2 + (e>>1), j2 = e&1
//   k0 = s*16 + (t&3)*2 + j2*8,  n = w*64 + u*8 + (t>>2)
//   val = half2(W[k0][n], W[k0+1][n]),  W[k][n] = k<256 ? Wih[n][k] : Whh[n][k-256]
// Small GEMM fragments (uint2 per (lane,tile,step)):
//   G1 (gamma_h|gamma_x: K=128, N=384=Wdh(256)|Wdx(128)):  i=((w*8+s)*3+uu)*64 + t*2 + j2
//   G2a (x_h: K=256,N=128, warps 0-7):  i=((w*16+s)*2+uu)*64 + t*2 + j2
//   G2b (alpha: K=256,N=128, warps 8-15): same with w-8
//   G3 (z_h: K=128,N=128): i=(w*8+s)*64 + t*2 + j2
#define SMG1  262144
#define SMG2A 286720
#define SMG2B 303104
#define SMG3  319488
#define WTB_TOTAL 327680
__device__ uint32_t g_wtb_u[WTB_TOTAL];
// Combined gate bias bih+bhh
__device__ float g_gb[4 * HH];

__device__ __forceinline__ float sigf(float x) { return 1.f / (1.f + __expf(-x)); }
__device__ __forceinline__ float tanh_fast(float x) { return 2.f / (1.f + __expf(-2.f * x)) - 1.f; }

// Full m16n8k16 HMMA (all 16 A-rows live).
__device__ __forceinline__ void mmaf(float& c0, float& c1, float& c2, float& c3,
                                     uint32_t a0, uint32_t a1, uint32_t a2, uint32_t a3,
                                     uint32_t b0, uint32_t b1) {
    asm volatile(
        "mma.sync.aligned.m16n8k16.row.col.f32.f16.f16.f32 "
        "{%0,%1,%2,%3}, {%4,%5,%6,%7}, {%8,%9}, {%0,%1,%2,%3};"
        : "+f"(c0), "+f"(c1), "+f"(c2), "+f"(c3)
        : "r"(a0), "r"(a1), "r"(a2), "r"(a3), "r"(b0), "r"(b1));
}

__device__ __forceinline__ uint32_t pack_pair(float lo, float hi) {
    uint32_t l = __half_as_ushort(__float2half_rn(lo));
    uint32_t h = __half_as_ushort(__float2half_rn(hi));
    return l | (h << 16);
}

// ---- fused prologue: all fragment packing + bias combine, ONE launch ----
#define PREP_TOTAL (WTB_TOTAL + 1024)
__global__ void prep_kernel(const float* __restrict__ Wdh, const float* __restrict__ Wdx,
                            const float* __restrict__ Wh,  const float* __restrict__ Wf,
                            const float* __restrict__ Wc,  const float* __restrict__ Wih,
                            const float* __restrict__ Whh, const float* __restrict__ bih,
                            const float* __restrict__ bhh) {
    int idx = blockIdx.x * blockDim.x + threadIdx.x;
    if (idx >= PREP_TOTAL) return;
    if (idx < 262144) {                    // gates, coalesced fragment layout
        int e = idx & 3, t = (idx >> 2) & 31, q = (idx >> 7) & 3;
        int s = (idx >> 9) & 31, w = (idx >> 14) & 15;
        int u = q * 2 + (e >> 1), j2 = e & 1;
        int k0 = s * 16 + (t & 3) * 2 + j2 * 8;
        int n  = w * 64 + u * 8 + (t >> 2);
        float lo, hi;
        if (k0 < 256) { lo = Wih[n * 256 + k0];       hi = Wih[n * 256 + k0 + 1]; }
        else          { lo = Whh[n * 256 + k0 - 256]; hi = Whh[n * 256 + k0 - 255]; }
        g_wtb_u[idx] = pack_pair(lo, hi);
    } else if (idx < SMG2A) {              // G1
        int i = idx - SMG1;
        int j2 = i & 1, t = (i >> 1) & 31;
        int rest = i >> 6, uu = rest % 3, ws = rest / 3;
        int s = ws & 7, w = ws >> 3;
        int tile = w * 3 + uu;
        int n = tile * 8 + (t >> 2);
        int k0 = s * 16 + (t & 3) * 2 + j2 * 8;
        float lo, hi;
        if (n < 256) { lo = Wdh[n * 128 + k0]; hi = Wdh[n * 128 + k0 + 1]; }
        else { int n2 = n - 256; lo = Wdx[n2 * 128 + k0]; hi = Wdx[n2 * 128 + k0 + 1]; }
        g_wtb_u[idx] = pack_pair(lo, hi);
    } else if (idx < SMG2B) {              // G2a: Wh
        int i = idx - SMG2A;
        int j2 = i & 1, t = (i >> 1) & 31;
        int rest = i >> 6, uu = rest & 1, ws = rest >> 1;
        int s = ws & 15, w = ws >> 4;
        int n = (w * 2 + uu) * 8 + (t >> 2);
        int k0 = s * 16 + (t & 3) * 2 + j2 * 8;
        g_wtb_u[idx] = pack_pair(Wh[n * 256 + k0], Wh[n * 256 + k0 + 1]);
    } else if (idx < SMG3) {               // G2b: Wc (input = gx || m)
        int i = idx - SMG2B;
        int j2 = i & 1, t = (i >> 1) & 31;
        int rest = i >> 6, uu = rest & 1, ws = rest >> 1;
        int s = ws & 15, w = ws >> 4;
        int n = (w * 2 + uu) * 8 + (t >> 2);
        int k0 = s * 16 + (t & 3) * 2 + j2 * 8;
        g_wtb_u[idx] = pack_pair(Wc[n * 256 + k0], Wc[n * 256 + k0 + 1]);
    } else if (idx < WTB_TOTAL) {          // G3: Wf
        int i = idx - SMG3;
        int j2 = i & 1, t = (i >> 1) & 31;
        int rest = i >> 6, s = rest & 7, w = rest >> 3;
        int n = w * 8 + (t >> 2);
        int k0 = s * 16 + (t & 3) * 2 + j2 * 8;
        g_wtb_u[idx] = pack_pair(Wf[n * 128 + k0], Wf[n * 128 + k0 + 1]);
    } else {                               // combined gate bias
        int i = idx - WTB_TOTAL;
        g_gb[i] = bih[i] + bhh[i];
    }
}

// ---- persistent RITS scan. Each CTA owns 16 batch rows for all 512 steps. ----
// fp32 activations pitch-16: arr[k*16 + r].
// fp16 activation shadow actH[16][PH]: per row r:
//   [0:128) c_c | [128:256) m | [256:512) hd | [512:640) gx | [640:768) m copy | [768:896) dsa | [896:1024) x_c
#define PH 1032   // pitch in halves (2064 B -> 4-bank shift per row, conflict-free)
__global__ void __launch_bounds__(NTHR, 1) rits_kernel(
    const float* __restrict__ values, const int* __restrict__ masks, const float* __restrict__ deltas,
    const float* __restrict__ bdh, const float* __restrict__ bdx,
    const float* __restrict__ bh,  const float* __restrict__ bf_,
    const float* __restrict__ bc,
    const float* __restrict__ Wo,  const float* __restrict__ bo,
    float* __restrict__ out)
{
    extern __shared__ float smem[];
    float* hs  = smem;            // [H*16]
    float* cs  = hs  + 4096;      // [H*16]
    float* xs  = cs  + 4096;      // [D*16]
    float* msa = xs  + 2048;      // [D*16]
    float* xh  = msa + 2048;      // [D*16]
    float* al  = xh  + 2048;      // [D*16]
    float* zh  = al  + 2048;      // [D*16]
    float* gt  = zh  + 2048;      // [4H*16]
    __half* actH = (__half*)(gt + 16384);  // [16][PH]

    const int j = threadIdx.x;
    const int w = j >> 5, tl = j & 31;
    const int rr = tl >> 2, c4 = tl & 3;
    const int rowbase = blockIdx.x * NROWS;
    float* out_imp = out + BB * CCLS;

    for (int i = j; i < 8192; i += NTHR) { hs[i] = 0.f; }   // hs + cs contiguous
    // (hs covers [0,4096), cs [4096,8192) — both zeroed by the loop above)

    // input prefetch registers (double-buffer in regs across steps)
    float pv[4], pm[4], pd[4];
    {
        const int base0 = rowbase * (TT * DD);
        #pragma unroll
        for (int i = 0; i < 4; ++i) {
            int idx = j + i * NTHR;
            int r = idx >> 7, k = idx & 127;
            int g = base0 + r * (TT * DD) + k;
            pv[i] = values[g]; pm[i] = (float)masks[g]; pd[i] = deltas[g];
        }
    }
    __syncthreads();

    for (int t = 0; t < TT; ++t) {
        // ---- phase 1: commit prefetched x, m, d ----
        #pragma unroll
        for (int i = 0; i < 4; ++i) {
            int idx = j + i * NTHR;
            int r = idx >> 7, k = idx & 127;
            int si = k * 16 + r;
            xs[si] = pv[i]; msa[si] = pm[i];
            __half mh = __float2half(pm[i]);
            actH[r * PH + 128 + k] = mh;                    // m (gates)
            actH[r * PH + 640 + k] = mh;                    // m (alpha)
            actH[r * PH + 768 + k] = __float2half(pd[i]);   // dsa
        }
        __syncthreads();

        // issue next step's input loads
        if (t + 1 < TT) {
            const int base0 = rowbase * (TT * DD) + (t + 1) * DD;
            #pragma unroll
            for (int i = 0; i < 4; ++i) {
                int idx = j + i * NTHR;
                int r = idx >> 7, k = idx & 127;
                int g = base0 + r * (TT * DD) + k;
                pv[i] = values[g]; pm[i] = (float)masks[g]; pd[i] = deltas[g];
            }
        }

        // ---- phase 2 (G1): gamma_h | gamma_x via HMMA; K=128, N=384; 3 tiles/warp ----
        {
            float acc[3][4];
            #pragma unroll
            for (int uu = 0; uu < 3; ++uu)
                #pragma unroll
                for (int c = 0; c < 4; ++c) acc[uu][c] = 0.f;
            const __half* aL = actH + rr * PH + 768 + c4 * 2;
            const __half* aH = actH + (rr + 8) * PH + 768 + c4 * 2;
            const uint2* fb = (const uint2*)(g_wtb_u + SMG1);
            #pragma unroll 2
            for (int s = 0; s < 8; ++s) {
                uint32_t a0 = *(const uint32_t*)(aL + s * 16);
                uint32_t a1 = *(const uint32_t*)(aH + s * 16);
                uint32_t a2 = *(const uint32_t*)(aL + s * 16 + 8);
                uint32_t a3 = *(const uint32_t*)(aH + s * 16 + 8);
                const uint2* wp = fb + ((w * 8 + s) * 3) * 32 + tl;
                uint2 b0 = wp[0], b1 = wp[32], b2 = wp[64];
                mmaf(acc[0][0], acc[0][1], acc[0][2], acc[0][3], a0, a1, a2, a3, b0.x, b0.y);
                mmaf(acc[1][0], acc[1][1], acc[1][2], acc[1][3], a0, a1, a2, a3, b1.x, b1.y);
                mmaf(acc[2][0], acc[2][1], acc[2][2], acc[2][3], a0, a1, a2, a3, b2.x, b2.y);
            }
            #pragma unroll
            for (int uu = 0; uu < 3; ++uu) {
                int tile = w * 3 + uu;
                int n0 = tile * 8 + c4 * 2;
                #pragma unroll
                for (int half = 0; half < 2; ++half) {
                    int r = rr + half * 8;
                    #pragma unroll
                    for (int c = 0; c < 2; ++c) {
                        int n = n0 + c;
                        float v = acc[uu][half * 2 + c];
                        if (tile < 32) {
                            float gam = __expf(-fmaxf(v + bdh[n], 0.f));
                            float hv = hs[n * 16 + r] * gam;
                            actH[r * PH + 256 + n] = __float2half(hv);
                        } else {
                            int n2 = n - 256;
                            float gxv = __expf(-fmaxf(v + bdx[n2], 0.f));
                            actH[r * PH + 512 + n2] = __float2half(gxv);
                        }
                    }
                }
            }
        }
        __syncthreads();

        // ---- phase 3 (G2): x_h (warps 0-7, A=hd) | alpha (warps 8-15, A=gx||m) ----
        {
            float acc[2][4];
            #pragma unroll
            for (int uu = 0; uu < 2; ++uu)
                #pragma unroll
                for (int c = 0; c < 4; ++c) acc[uu][c] = 0.f;
            const bool isA = (w < 8);
            const int wl = isA ? w : (w - 8);
            const int aoff = isA ? 256 : 512;
            const __half* aL = actH + rr * PH + aoff + c4 * 2;
            const __half* aH = actH + (rr + 8) * PH + aoff + c4 * 2;
            const uint2* fb = (const uint2*)(g_wtb_u + (isA ? SMG2A : SMG2B));
            #pragma unroll 4
            for (int s = 0; s < 16; ++s) {
                uint32_t a0 = *(const uint32_t*)(aL + s * 16);
                uint32_t a1 = *(const uint32_t*)(aH + s * 16);
                uint32_t a2 = *(const uint32_t*)(aL + s * 16 + 8);
                uint32_t a3 = *(const uint32_t*)(aH + s * 16 + 8);
                const uint2* wp = fb + ((wl * 16 + s) * 2) * 32 + tl;
                uint2 b0 = wp[0], b1 = wp[32];
                mmaf(acc[0][0], acc[0][1], acc[0][2], acc[0][3], a0, a1, a2, a3, b0.x, b0.y);
                mmaf(acc[1][0], acc[1][1], acc[1][2], acc[1][3], a0, a1, a2, a3, b1.x, b1.y);
            }
            #pragma unroll
            for (int uu = 0; uu < 2; ++uu) {
                int n0 = (wl * 2 + uu) * 8 + c4 * 2;
                #pragma unroll
                for (int half = 0; half < 2; ++half) {
                    int r = rr + half * 8;
                    #pragma unroll
                    for (int c = 0; c < 2; ++c) {
                        int n = n0 + c;
                        float v = acc[uu][half * 2 + c];
                        if (isA) xh[n * 16 + r] = v + bh[n];
                        else     al[n * 16 + r] = v + bc[n];
                    }
                }
            }
        }
        __syncthreads();

        // ---- phase 3.5: x_c = m*x + (1-m)*x_h -> fp16 shadow ----
        #pragma unroll
        for (int i = 0; i < 4; ++i) {
            int idx = j + i * NTHR;
            float mv = msa[idx];
            float xc = mv * xs[idx] + (1.f - mv) * xh[idx];
            int k = idx >> 4, r = idx & 15;
            actH[r * PH + 896 + k] = __float2half(xc);
        }
        __syncthreads();

        // ---- phase 4 (G3): z_h via HMMA; K=128, N=128; 1 tile/warp ----
        {
            float acc0 = 0.f, acc1 = 0.f, acc2 = 0.f, acc3 = 0.f;
            const __half* aL = actH + rr * PH + 896 + c4 * 2;
            const __half* aH = actH + (rr + 8) * PH + 896 + c4 * 2;
            const uint2* fb = (const uint2*)(g_wtb_u + SMG3);
            #pragma unroll 2
            for (int s = 0; s < 8; ++s) {
                uint32_t a0 = *(const uint32_t*)(aL + s * 16);
                uint32_t a1 = *(const uint32_t*)(aH + s * 16);
                uint32_t a2 = *(const uint32_t*)(aL + s * 16 + 8);
                uint32_t a3 = *(const uint32_t*)(aH + s * 16 + 8);
                uint2 b0 = fb[(w * 8 + s) * 32 + tl];
                mmaf(acc0, acc1, acc2, acc3, a0, a1, a2, a3, b0.x, b0.y);
            }
            int n0 = w * 8 + c4 * 2;
            zh[n0 * 16 + rr]            = acc0 + bf_[n0];
            zh[(n0 + 1) * 16 + rr]      = acc1 + bf_[n0 + 1];
            zh[n0 * 16 + rr + 8]        = acc2 + bf_[n0];
            zh[(n0 + 1) * 16 + rr + 8]  = acc3 + bf_[n0 + 1];
        }
        __syncthreads();

        // ---- phase 5: c_h, c_c; write imputation + fp16 c_c ----
        {
            const int base0 = rowbase * (TT * DD) + t * DD;
            #pragma unroll
            for (int i = 0; i < 4; ++i) {
                int idx2 = j + i * NTHR;
                int r = idx2 >> 7, k = idx2 & 127;
                int si = k * 16 + r;
                float a = al[si], zv = zh[si], xhv = xh[si], mv = msa[si], xv = xs[si];
                float ch = a * zv + (1.f - a) * xhv;
                float cc = mv * xv + (1.f - mv) * ch;
                actH[r * PH + k] = __float2half(cc);
                out_imp[base0 + r * (TT * DD) + k] = cc;
            }
        }
        __syncthreads();

        // ---- phase 6: gates via HMMA (per-warp 64-col slice, coalesced frags) ----
        {
            float acc[8][4];
            #pragma unroll
            for (int u = 0; u < 8; ++u)
                #pragma unroll
                for (int c = 0; c < 4; ++c) acc[u][c] = 0.f;
            const uint4* fragbase = (const uint4*)g_wtb_u + (size_t)w * 4096;
            const __half* aL = actH + rr * PH + c4 * 2;
            const __half* aH = actH + (rr + 8) * PH + c4 * 2;
            #pragma unroll 4
            for (int s = 0; s < 32; ++s) {
                uint32_t a0 = *(const uint32_t*)(aL + s * 16);
                uint32_t a1 = *(const uint32_t*)(aH + s * 16);
                uint32_t a2 = *(const uint32_t*)(aL + s * 16 + 8);
                uint32_t a3 = *(const uint32_t*)(aH + s * 16 + 8);
                const uint4* wp = fragbase + s * 128 + tl;
                uint4 q0 = wp[0], q1 = wp[32], q2 = wp[64], q3 = wp[96];
                mmaf(acc[0][0], acc[0][1], acc[0][2], acc[0][3], a0, a1, a2, a3, q0.x, q0.y);
                mmaf(acc[1][0], acc[1][1], acc[1][2], acc[1][3], a0, a1, a2, a3, q0.z, q0.w);
                mmaf(acc[2][0], acc[2][1], acc[2][2], acc[2][3], a0, a1, a2, a3, q1.x, q1.y);
                mmaf(acc[3][0], acc[3][1], acc[3][2], acc[3][3], a0, a1, a2, a3, q1.z, q1.w);
                mmaf(acc[4][0], acc[4][1], acc[4][2], acc[4][3], a0, a1, a2, a3, q2.x, q2.y);
                mmaf(acc[5][0], acc[5][1], acc[5][2], acc[5][3], a0, a1, a2, a3, q2.z, q2.w);
                mmaf(acc[6][0], acc[6][1], acc[6][2], acc[6][3], a0, a1, a2, a3, q3.x, q3.y);
                mmaf(acc[7][0], acc[7][1], acc[7][2], acc[7][3], a0, a1, a2, a3, q3.z, q3.w);
            }
            #pragma unroll
            for (int u = 0; u < 8; ++u) {
                int n0 = w * 64 + u * 8 + c4 * 2;
                float b0v = g_gb[n0], b1v = g_gb[n0 + 1];
                gt[n0 * 16 + rr]           = acc[u][0] + b0v;
                gt[(n0 + 1) * 16 + rr]     = acc[u][1] + b1v;
                gt[n0 * 16 + rr + 8]       = acc[u][2] + b0v;
                gt[(n0 + 1) * 16 + rr + 8] = acc[u][3] + b1v;
            }
        }
        __syncthreads();

        // ---- phase 7: LSTM cell update (2 threads per h-column, 8 rows each) ----
        {
            const int n = j & 255, half = j >> 8;
            #pragma unroll
            for (int r0 = 0; r0 < 8; ++r0) {
                int r = half * 8 + r0;
                float ig = sigf(gt[n * 16 + r]);
                float fg = sigf(gt[(n + HH) * 16 + r]);
                float gg = tanh_fast(gt[(n + 2 * HH) * 16 + r]);
                float og = sigf(gt[(n + 3 * HH) * 16 + r]);
                float cn = fg * cs[n * 16 + r] + ig * gg;
                cs[n * 16 + r] = cn;
                hs[n * 16 + r] = og * tanh_fast(cn);
            }
        }
        __syncthreads();
    }

    // ---- final: y_h = h@Wo.T + bo ----
    if (j < NROWS * CCLS) {
        int r = j >> 1, cl = j & 1;
        float acc = bo[cl];
        #pragma unroll 8
        for (int k = 0; k < HH; ++k) acc += hs[k * 16 + r] * Wo[cl * HH + k];
        out[(rowbase + r) * CCLS + cl] = acc;
    }
}

extern "C" void kernel_launch(void* const* d_in, const int* in_sizes, int n_in,
                              void* d_out, int out_size) {
    const float* values = (const float*)d_in[0];
    const int*   masks  = (const int*)  d_in[1];
    const float* deltas = (const float*)d_in[2];
    const float* Wdh = (const float*)d_in[3];
    const float* bdh = (const float*)d_in[4];
    const float* Wdx = (const float*)d_in[5];
    const float* bdx = (const float*)d_in[6];
    const float* Wh  = (const float*)d_in[7];
    const float* bh  = (const float*)d_in[8];
    const float* Wf  = (const float*)d_in[9];
    const float* bf_ = (const float*)d_in[10];
    const float* Wc  = (const float*)d_in[11];
    const float* bc  = (const float*)d_in[12];
    const float* Wih = (const float*)d_in[13];
    const float* bih = (const float*)d_in[14];
    const float* Whh = (const float*)d_in[15];
    const float* bhh = (const float*)d_in[16];
    const float* Wo  = (const float*)d_in[17];
    const float* bo  = (const float*)d_in[18];
    float* out = (float*)d_out;

    prep_kernel<<<(PREP_TOTAL + 255) / 256, 256>>>(Wdh, Wdx, Wh, Wf, Wc, Wih, Whh, bih, bhh);

    // smem: 34816 floats (139264 B) + actH 16*1032 halves (33024 B) = 172288 B
    size_t smem_bytes = 34816 * sizeof(float) + 16 * PH * sizeof(__half);
    cudaFuncSetAttribute(rits_kernel, cudaFuncAttributeMaxDynamicSharedMemorySize,
                         (int)smem_bytes);
    rits_kernel<<<NCTA, NTHR, smem_bytes>>>(values, masks, deltas,
                                            bdh, bdx, bh, bf_, bc,
                                            Wo, bo, out);
}

// round 9
// speedup vs baseline: 1.4369x; 1.4369x over previous
#include <cuda_runtime.h>
#include <cuda_bf16.h>
#include <cuda_fp16.h>
#include <cstdint>

// Problem dims
#define BB 1024
#define TT 512
#define DD 128
#define HH 256
#define CCLS 2
#define NROWS 8
#define NCTA (BB / NROWS)   // 128 CTAs
#define NTHR 1024

// ---- fragment-packed fp16 weights (device global; no allocations allowed) ----
// Gates [0, 262144) u32, coalesced layout (packed for 16 "macro-warps"):
//   i = ((((w*32 + s)*4 + q)*32 + t)*4 + e),  u = q*2 + (e>>1), j2 = e&1
//   k0 = s*16 + (t&3)*2 + j2*8,  n = w*64 + u*8 + (t>>2)
//   val = half2(W[k0][n], W[k0+1][n]),  W[k][n] = k<256 ? Wih[n][k] : Whh[n][k-256]
// A 32-warp reader uses w_old = w>>1 and q-pair (w&1)*2 .. (w&1)*2+1.
// Small GEMM fragments (uint2 per (lane,tile,step)), tile T decomposed per layout:
//   G1 (gamma_h|gamma_x: K=128, N=384):  i=((cw*8+s)*3+cu)*64 + t*2 + j2, T=cw*3+cu
//   G2a (x_h: K=256,N=128):  i=((wl*16+s)*2+uu)*64 + t*2 + j2, T=wl*2+uu
//   G2b (alpha: K=256,N=128): same layout, separate base
//   G3 (z_h: K=128,N=128): i=(T*8+s)*64 + t*2 + j2
#define SMG1  262144
#define SMG2A 286720
#define SMG2B 303104
#define SMG3  319488
#define WTB_TOTAL 327680
__device__ uint32_t g_wtb_u[WTB_TOTAL];
// Combined gate bias bih+bhh
__device__ float g_gb[4 * HH];

__device__ __forceinline__ float sigf(float x) { return 1.f / (1.f + __expf(-x)); }
__device__ __forceinline__ float tanh_fast(float x) { return 2.f / (1.f + __expf(-2.f * x)) - 1.f; }

// m16n8k16 HMMA; A rows 8-15 zero, c2/c3 discarded.
__device__ __forceinline__ void mma1(float& c0, float& c1, float& c2, float& c3,
                                     uint32_t a0, uint32_t a2, uint32_t b0, uint32_t b1) {
    asm volatile(
        "mma.sync.aligned.m16n8k16.row.col.f32.f16.f16.f32 "
        "{%0,%1,%2,%3}, {%4,%5,%6,%7}, {%8,%9}, {%0,%1,%2,%3};"
        : "+f"(c0), "+f"(c1), "+f"(c2), "+f"(c3)
        : "r"(a0), "r"(0u), "r"(a2), "r"(0u), "r"(b0), "r"(b1));
}

__device__ __forceinline__ uint32_t pack_pair(float lo, float hi) {
    uint32_t l = __half_as_ushort(__float2half_rn(lo));
    uint32_t h = __half_as_ushort(__float2half_rn(hi));
    return l | (h << 16);
}

// ---- fused prologue: all fragment packing + bias combine, ONE launch ----
#define PREP_TOTAL (WTB_TOTAL + 1024)
__global__ void prep_kernel(const float* __restrict__ Wdh, const float* __restrict__ Wdx,
                            const float* __restrict__ Wh,  const float* __restrict__ Wf,
                            const float* __restrict__ Wc,  const float* __restrict__ Wih,
                            const float* __restrict__ Whh, const float* __restrict__ bih,
                            const float* __restrict__ bhh) {
    int idx = blockIdx.x * blockDim.x + threadIdx.x;
    if (idx >= PREP_TOTAL) return;
    if (idx < 262144) {                    // gates, coalesced fragment layout
        int e = idx & 3, t = (idx >> 2) & 31, q = (idx >> 7) & 3;
        int s = (idx >> 9) & 31, w = (idx >> 14) & 15;
        int u = q * 2 + (e >> 1), j2 = e & 1;
        int k0 = s * 16 + (t & 3) * 2 + j2 * 8;
        int n  = w * 64 + u * 8 + (t >> 2);
        float lo, hi;
        if (k0 < 256) { lo = Wih[n * 256 + k0];       hi = Wih[n * 256 + k0 + 1]; }
        else          { lo = Whh[n * 256 + k0 - 256]; hi = Whh[n * 256 + k0 - 255]; }
        g_wtb_u[idx] = pack_pair(lo, hi);
    } else if (idx < SMG2A) {              // G1
        int i = idx - SMG1;
        int j2 = i & 1, t = (i >> 1) & 31;
        int rest = i >> 6, uu = rest % 3, ws = rest / 3;
        int s = ws & 7, w = ws >> 3;
        int tile = w * 3 + uu;
        int n = tile * 8 + (t >> 2);
        int k0 = s * 16 + (t & 3) * 2 + j2 * 8;
        float lo, hi;
        if (n < 256) { lo = Wdh[n * 128 + k0]; hi = Wdh[n * 128 + k0 + 1]; }
        else { int n2 = n - 256; lo = Wdx[n2 * 128 + k0]; hi = Wdx[n2 * 128 + k0 + 1]; }
        g_wtb_u[idx] = pack_pair(lo, hi);
    } else if (idx < SMG2B) {              // G2a: Wh
        int i = idx - SMG2A;
        int j2 = i & 1, t = (i >> 1) & 31;
        int rest = i >> 6, uu = rest & 1, ws = rest >> 1;
        int s = ws & 15, w = ws >> 4;
        int n = (w * 2 + uu) * 8 + (t >> 2);
        int k0 = s * 16 + (t & 3) * 2 + j2 * 8;
        g_wtb_u[idx] = pack_pair(Wh[n * 256 + k0], Wh[n * 256 + k0 + 1]);
    } else if (idx < SMG3) {               // G2b: Wc (input = gx || m)
        int i = idx - SMG2B;
        int j2 = i & 1, t = (i >> 1) & 31;
        int rest = i >> 6, uu = rest & 1, ws = rest >> 1;
        int s = ws & 15, w = ws >> 4;
        int n = (w * 2 + uu) * 8 + (t >> 2);
        int k0 = s * 16 + (t & 3) * 2 + j2 * 8;
        g_wtb_u[idx] = pack_pair(Wc[n * 256 + k0], Wc[n * 256 + k0 + 1]);
    } else if (idx < WTB_TOTAL) {          // G3: Wf
        int i = idx - SMG3;
        int j2 = i & 1, t = (i >> 1) & 31;
        int rest = i >> 6, s = rest & 7, w = rest >> 3;
        int n = w * 8 + (t >> 2);
        int k0 = s * 16 + (t & 3) * 2 + j2 * 8;
        g_wtb_u[idx] = pack_pair(Wf[n * 128 + k0], Wf[n * 128 + k0 + 1]);
    } else {                               // combined gate bias
        int i = idx - WTB_TOTAL;
        g_gb[i] = bih[i] + bhh[i];
    }
}

// ---- persistent RITS scan: 128 CTAs x 8 rows, 1024 threads (32 warps). ----
// fp16 activation shadow actH[8][PH]: per row r:
//   [0:128) c_c | [128:256) m | [256:512) hd | [512:640) gx | [640:768) m copy | [768:896) dsa | [896:1024) x_c
#define PH 1032
__global__ void __launch_bounds__(NTHR, 1) rits_kernel(
    const float* __restrict__ values, const int* __restrict__ masks, const float* __restrict__ deltas,
    const float* __restrict__ bdh, const float* __restrict__ bdx,
    const float* __restrict__ bh,  const float* __restrict__ bf_,
    const float* __restrict__ bc,
    const float* __restrict__ Wo,  const float* __restrict__ bo,
    float* __restrict__ out)
{
    extern __shared__ float smem[];
    float* hs  = smem;            // [H*8]
    float* cs  = hs  + 2048;      // [H*8]
    float* xs  = cs  + 2048;      // [D*8]
    float* msa = xs  + 1024;      // [D*8]
    float* xh  = msa + 1024;      // [D*8]
    float* al  = xh  + 1024;      // [D*8]
    float* zh  = al  + 1024;      // [D*8]
    float* gt  = zh  + 1024;      // [4H*8]
    __half* actH = (__half*)(gt + 8192);  // [8][PH]

    const int j = threadIdx.x;
    const int w = j >> 5, tl = j & 31;
    const int rr = tl >> 2, c4 = tl & 3;
    const int rowbase = blockIdx.x * NROWS;
    float* out_imp = out + BB * CCLS;

    for (int i = j; i < 4096; i += NTHR) { hs[i] = 0.f; }  // hs+cs contiguous zero

    // input prefetch (1 elem/thread)
    float pv, pm, pd;
    {
        const int r = j >> 7, k = j & 127;
        const int g = rowbase * (TT * DD) + r * (TT * DD) + k;
        pv = values[g]; pm = (float)masks[g]; pd = deltas[g];
    }
    __syncthreads();

    const int r1 = j >> 7, k1 = j & 127;          // phase-1/5 mapping
    for (int t = 0; t < TT; ++t) {
        // ---- phase 1: commit prefetched x, m, d ----
        {
            int si = k1 * 8 + r1;
            xs[si] = pv; msa[si] = pm;
            __half mh = __float2half(pm);
            actH[r1 * PH + 128 + k1] = mh;
            actH[r1 * PH + 640 + k1] = mh;
            actH[r1 * PH + 768 + k1] = __float2half(pd);
        }
        __syncthreads();

        // issue next step's input loads
        if (t + 1 < TT) {
            int g = rowbase * (TT * DD) + r1 * (TT * DD) + (t + 1) * DD + k1;
            pv = values[g]; pm = (float)masks[g]; pd = deltas[g];
        }

        // ---- phase 2 (G1): gamma_h | gamma_x; 48 tiles: T=w (all), T=32+w (w<16) ----
        {
            const __half* arow = actH + rr * PH + 768 + c4 * 2;
            const uint2* fb = (const uint2*)(g_wtb_u + SMG1);
            float acc0 = 0.f, acc1 = 0.f, accB0 = 0.f, accB1 = 0.f;
            float d2 = 0.f, d3 = 0.f;
            const int T1 = w;
            const int cw1 = T1 / 3, cu1 = T1 - cw1 * 3;
            const int T2 = 32 + w;
            const int cw2 = T2 / 3, cu2 = T2 - cw2 * 3;
            const bool two = (w < 16);
            #pragma unroll 2
            for (int s = 0; s < 8; ++s) {
                uint32_t a0 = *(const uint32_t*)(arow + s * 16);
                uint32_t a2 = *(const uint32_t*)(arow + s * 16 + 8);
                uint2 b0 = fb[((cw1 * 8 + s) * 3 + cu1) * 32 + tl];
                mma1(acc0, acc1, d2, d3, a0, a2, b0.x, b0.y);
                if (two) {
                    uint2 b1 = fb[((cw2 * 8 + s) * 3 + cu2) * 32 + tl];
                    mma1(accB0, accB1, d2, d3, a0, a2, b1.x, b1.y);
                }
            }
            // epilogue tile 1 (always gamma_h: T1 = w < 32)
            {
                int n0 = T1 * 8 + c4 * 2;
                #pragma unroll
                for (int c = 0; c < 2; ++c) {
                    int n = n0 + c;
                    float v = (c == 0) ? acc0 : acc1;
                    float gam = __expf(-fmaxf(v + bdh[n], 0.f));
                    float hv = hs[n * 8 + rr] * gam;
                    actH[rr * PH + 256 + n] = __float2half(hv);
                }
            }
            if (two) {       // tile 2: gamma_x (T2 in 32..47)
                int n0 = T2 * 8 - 256 + c4 * 2;
                #pragma unroll
                for (int c = 0; c < 2; ++c) {
                    int n2 = n0 + c;
                    float v = (c == 0) ? accB0 : accB1;
                    float gxv = __expf(-fmaxf(v + bdx[n2], 0.f));
                    actH[rr * PH + 512 + n2] = __float2half(gxv);
                }
            }
        }
        __syncthreads();

        // ---- phase 3 (G2): x_h (warps 0-15) | alpha (warps 16-31); 1 tile/warp ----
        {
            const bool isA = (w < 16);
            const int T = isA ? w : (w - 16);
            const int wl = T >> 1, uu = T & 1;
            const __half* arow = actH + rr * PH + (isA ? 256 : 512) + c4 * 2;
            const uint2* fb = (const uint2*)(g_wtb_u + (isA ? SMG2A : SMG2B));
            float acc0 = 0.f, acc1 = 0.f, d2 = 0.f, d3 = 0.f;
            #pragma unroll 4
            for (int s = 0; s < 16; ++s) {
                uint32_t a0 = *(const uint32_t*)(arow + s * 16);
                uint32_t a2 = *(const uint32_t*)(arow + s * 16 + 8);
                uint2 b0 = fb[((wl * 16 + s) * 2 + uu) * 32 + tl];
                mma1(acc0, acc1, d2, d3, a0, a2, b0.x, b0.y);
            }
            int n0 = T * 8 + c4 * 2;
            if (isA) {
                xh[n0 * 8 + rr]       = acc0 + bh[n0];
                xh[(n0 + 1) * 8 + rr] = acc1 + bh[n0 + 1];
            } else {
                al[n0 * 8 + rr]       = acc0 + bc[n0];
                al[(n0 + 1) * 8 + rr] = acc1 + bc[n0 + 1];
            }
        }
        __syncthreads();

        // ---- phase 3.5: x_c = m*x + (1-m)*x_h -> fp16 shadow (1 elem/thread) ----
        {
            float mv = msa[j];
            float xc = mv * xs[j] + (1.f - mv) * xh[j];
            int k = j >> 3, r = j & 7;
            actH[r * PH + 896 + k] = __float2half(xc);
        }
        __syncthreads();

        // ---- phase 4 (G3): z_h; warps 0-15, 1 tile each ----
        if (w < 16) {
            float acc0 = 0.f, acc1 = 0.f, d2 = 0.f, d3 = 0.f;
            const __half* arow = actH + rr * PH + 896 + c4 * 2;
            const uint2* fb = (const uint2*)(g_wtb_u + SMG3);
            #pragma unroll 2
            for (int s = 0; s < 8; ++s) {
                uint32_t a0 = *(const uint32_t*)(arow + s * 16);
                uint32_t a2 = *(const uint32_t*)(arow + s * 16 + 8);
                uint2 b0 = fb[(w * 8 + s) * 32 + tl];
                mma1(acc0, acc1, d2, d3, a0, a2, b0.x, b0.y);
            }
            int n0 = w * 8 + c4 * 2;
            zh[n0 * 8 + rr]       = acc0 + bf_[n0];
            zh[(n0 + 1) * 8 + rr] = acc1 + bf_[n0 + 1];
        }
        __syncthreads();

        // ---- phase 5: c_h, c_c; write imputation + fp16 c_c (1 elem/thread) ----
        {
            int si = k1 * 8 + r1;
            float a = al[si], zv = zh[si], xhv = xh[si], mv = msa[si], xv = xs[si];
            float ch = a * zv + (1.f - a) * xhv;
            float cc = mv * xv + (1.f - mv) * ch;
            actH[r1 * PH + k1] = __float2half(cc);
            out_imp[rowbase * (TT * DD) + r1 * (TT * DD) + t * DD + k1] = cc;
        }
        __syncthreads();

        // ---- phase 6: gates via HMMA; 32 cols/warp (2 uint4 per s-step) ----
        {
            float acc[4][2];
            #pragma unroll
            for (int u = 0; u < 4; ++u) { acc[u][0] = 0.f; acc[u][1] = 0.f; }
            float d2 = 0.f, d3 = 0.f;
            // old macro-warp = w>>1, q-pair = (w&1)*2
            const uint4* fragbase = (const uint4*)g_wtb_u
                                  + ((size_t)(w >> 1) * 32 * 4 + (size_t)(w & 1) * 2) * 32 + tl;
            const __half* arow = actH + rr * PH + c4 * 2;
            #pragma unroll 4
            for (int s = 0; s < 32; ++s) {
                uint32_t a0 = *(const uint32_t*)(arow + s * 16);
                uint32_t a2 = *(const uint32_t*)(arow + s * 16 + 8);
                const uint4* wp = fragbase + s * 128;
                uint4 q0 = wp[0], q1 = wp[32];
                mma1(acc[0][0], acc[0][1], d2, d3, a0, a2, q0.x, q0.y);
                mma1(acc[1][0], acc[1][1], d2, d3, a0, a2, q0.z, q0.w);
                mma1(acc[2][0], acc[2][1], d2, d3, a0, a2, q1.x, q1.y);
                mma1(acc[3][0], acc[3][1], d2, d3, a0, a2, q1.z, q1.w);
            }
            #pragma unroll
            for (int u = 0; u < 4; ++u) {
                int n0 = w * 32 + u * 8 + c4 * 2;
                gt[n0 * 8 + rr]       = acc[u][0] + g_gb[n0];
                gt[(n0 + 1) * 8 + rr] = acc[u][1] + g_gb[n0 + 1];
            }
        }
        __syncthreads();

        // ---- phase 7: LSTM cell update (4 threads per h-column, 2 rows each) ----
        {
            const int n = j & 255, quarter = j >> 8;
            #pragma unroll
            for (int r0 = 0; r0 < 2; ++r0) {
                int r = quarter * 2 + r0;
                float ig = sigf(gt[n * 8 + r]);
                float fg = sigf(gt[(n + HH) * 8 + r]);
                float gg = tanh_fast(gt[(n + 2 * HH) * 8 + r]);
                float og = sigf(gt[(n + 3 * HH) * 8 + r]);
                float cn = fg * cs[n * 8 + r] + ig * gg;
                cs[n * 8 + r] = cn;
                hs[n * 8 + r] = og * tanh_fast(cn);
            }
        }
        __syncthreads();
    }

    // ---- final: y_h = h@Wo.T + bo ----
    if (j < NROWS * CCLS) {
        int r = j >> 1, cl = j & 1;
        float acc = bo[cl];
        #pragma unroll 8
        for (int k = 0; k < HH; ++k) acc += hs[k * 8 + r] * Wo[cl * HH + k];
        out[(rowbase + r) * CCLS + cl] = acc;
    }
}

extern "C" void kernel_launch(void* const* d_in, const int* in_sizes, int n_in,
                              void* d_out, int out_size) {
    const float* values = (const float*)d_in[0];
    const int*   masks  = (const int*)  d_in[1];
    const float* deltas = (const float*)d_in[2];
    const float* Wdh = (const float*)d_in[3];
    const float* bdh = (const float*)d_in[4];
    const float* Wdx = (const float*)d_in[5];
    const float* bdx = (const float*)d_in[6];
    const float* Wh  = (const float*)d_in[7];
    const float* bh  = (const float*)d_in[8];
    const float* Wf  = (const float*)d_in[9];
    const float* bf_ = (const float*)d_in[10];
    const float* Wc  = (const float*)d_in[11];
    const float* bc  = (const float*)d_in[12];
    const float* Wih = (const float*)d_in[13];
    const float* bih = (const float*)d_in[14];
    const float* Whh = (const float*)d_in[15];
    const float* bhh = (const float*)d_in[16];
    const float* Wo  = (const float*)d_in[17];
    const float* bo  = (const float*)d_in[18];
    float* out = (float*)d_out;

    prep_kernel<<<(PREP_TOTAL + 255) / 256, 256>>>(Wdh, Wdx, Wh, Wf, Wc, Wih, Whh, bih, bhh);

    // smem: 17408 floats (69632 B) + actH 8*1032 halves (16512 B) = 86144 B
    size_t smem_bytes = 17408 * sizeof(float) + 8 * PH * sizeof(__half);
    cudaFuncSetAttribute(rits_kernel, cudaFuncAttributeMaxDynamicSharedMemorySize,
                         (int)smem_bytes);
    rits_kernel<<<NCTA, NTHR, smem_bytes>>>(values, masks, deltas,
                                            bdh, bdx, bh, bf_, bc,
                                            Wo, bo, out);
}

// round 10
// speedup vs baseline: 1.5413x; 1.0726x over previous
#include <cuda_runtime.h>
#include <cuda_bf16.h>
#include <cuda_fp16.h>
#include <cstdint>

// Problem dims
#define BB 1024
#define TT 512
#define DD 128
#define HH 256
#define CCLS 2
#define NROWS 8
#define NCTA (BB / NROWS)   // 128 CTAs
#define NTHR 1024

// ---- fragment-packed fp16 weights (device global; no allocations allowed) ----
// Gates [0, 262144) u32, gate-fused layout (32 warps):
//   i = (((w*32 + s)*2 + v)*128 + t*4 + e,  u = v*2 + (e>>1), j2 = e&1
//   warp w owns h-cols [w*8, w*8+8); tile u = gate index (0=i,1=f,2=g,3=o)
//   k0 = s*16 + (t&3)*2 + j2*8,  N = u*256 + w*8 + (t>>2)
//   val = half2(W[k0][N], W[k0+1][N]),  W[k][N] = k<256 ? Wih[N][k] : Whh[N][k-256]
// Small GEMM fragments (uint2 per (lane,tile,step)):
//   G1 (gamma_h|gamma_x: K=128, N=384):  i=((cw*8+s)*3+cu)*64 + t*2 + j2, T=cw*3+cu
//   G2a (x_h: K=256,N=128):  i=((wl*16+s)*2+uu)*64 + t*2 + j2, T=wl*2+uu
//   G2b (alpha: K=256,N=128): same layout, separate base
//   G3 (z_h: K=128,N=128): i=(T*8+s)*64 + t*2 + j2
#define SMG1  262144
#define SMG2A 286720
#define SMG2B 303104
#define SMG3  319488
#define WTB_TOTAL 327680
__device__ uint32_t g_wtb_u[WTB_TOTAL];
// Combined gate bias bih+bhh
__device__ float g_gb[4 * HH];

__device__ __forceinline__ float sigf(float x) { return 1.f / (1.f + __expf(-x)); }
__device__ __forceinline__ float tanh_fast(float x) { return 2.f / (1.f + __expf(-2.f * x)) - 1.f; }

// m16n8k16 HMMA; A rows 8-15 zero, c2/c3 discarded.
__device__ __forceinline__ void mma1(float& c0, float& c1, float& c2, float& c3,
                                     uint32_t a0, uint32_t a2, uint32_t b0, uint32_t b1) {
    asm volatile(
        "mma.sync.aligned.m16n8k16.row.col.f32.f16.f16.f32 "
        "{%0,%1,%2,%3}, {%4,%5,%6,%7}, {%8,%9}, {%0,%1,%2,%3};"
        : "+f"(c0), "+f"(c1), "+f"(c2), "+f"(c3)
        : "r"(a0), "r"(0u), "r"(a2), "r"(0u), "r"(b0), "r"(b1));
}

__device__ __forceinline__ uint32_t pack_pair(float lo, float hi) {
    uint32_t l = __half_as_ushort(__float2half_rn(lo));
    uint32_t h = __half_as_ushort(__float2half_rn(hi));
    return l | (h << 16);
}

// ---- fused prologue: all fragment packing + bias combine, ONE launch ----
#define PREP_TOTAL (WTB_TOTAL + 1024)
__global__ void prep_kernel(const float* __restrict__ Wdh, const float* __restrict__ Wdx,
                            const float* __restrict__ Wh,  const float* __restrict__ Wf,
                            const float* __restrict__ Wc,  const float* __restrict__ Wih,
                            const float* __restrict__ Whh, const float* __restrict__ bih,
                            const float* __restrict__ bhh) {
    int idx = blockIdx.x * blockDim.x + threadIdx.x;
    if (idx >= PREP_TOTAL) return;
    if (idx < 262144) {                    // gates, gate-fused coalesced layout
        int e = idx & 3, t = (idx >> 2) & 31, v = (idx >> 7) & 1;
        int s = (idx >> 8) & 31, w = (idx >> 13) & 31;
        int u = v * 2 + (e >> 1), j2 = e & 1;
        int k0 = s * 16 + (t & 3) * 2 + j2 * 8;
        int N  = u * 256 + w * 8 + (t >> 2);
        float lo, hi;
        if (k0 < 256) { lo = Wih[N * 256 + k0];       hi = Wih[N * 256 + k0 + 1]; }
        else          { lo = Whh[N * 256 + k0 - 256]; hi = Whh[N * 256 + k0 - 255]; }
        g_wtb_u[idx] = pack_pair(lo, hi);
    } else if (idx < SMG2A) {              // G1
        int i = idx - SMG1;
        int j2 = i & 1, t = (i >> 1) & 31;
        int rest = i >> 6, uu = rest % 3, ws = rest / 3;
        int s = ws & 7, w = ws >> 3;
        int tile = w * 3 + uu;
        int n = tile * 8 + (t >> 2);
        int k0 = s * 16 + (t & 3) * 2 + j2 * 8;
        float lo, hi;
        if (n < 256) { lo = Wdh[n * 128 + k0]; hi = Wdh[n * 128 + k0 + 1]; }
        else { int n2 = n - 256; lo = Wdx[n2 * 128 + k0]; hi = Wdx[n2 * 128 + k0 + 1]; }
        g_wtb_u[idx] = pack_pair(lo, hi);
    } else if (idx < SMG2B) {              // G2a: Wh
        int i = idx - SMG2A;
        int j2 = i & 1, t = (i >> 1) & 31;
        int rest = i >> 6, uu = rest & 1, ws = rest >> 1;
        int s = ws & 15, w = ws >> 4;
        int n = (w * 2 + uu) * 8 + (t >> 2);
        int k0 = s * 16 + (t & 3) * 2 + j2 * 8;
        g_wtb_u[idx] = pack_pair(Wh[n * 256 + k0], Wh[n * 256 + k0 + 1]);
    } else if (idx < SMG3) {               // G2b: Wc (input = gx || m)
        int i = idx - SMG2B;
        int j2 = i & 1, t = (i >> 1) & 31;
        int rest = i >> 6, uu = rest & 1, ws = rest >> 1;
        int s = ws & 15, w = ws >> 4;
        int n = (w * 2 + uu) * 8 + (t >> 2);
        int k0 = s * 16 + (t & 3) * 2 + j2 * 8;
        g_wtb_u[idx] = pack_pair(Wc[n * 256 + k0], Wc[n * 256 + k0 + 1]);
    } else if (idx < WTB_TOTAL) {          // G3: Wf
        int i = idx - SMG3;
        int j2 = i & 1, t = (i >> 1) & 31;
        int rest = i >> 6, s = rest & 7, w = rest >> 3;
        int n = w * 8 + (t >> 2);
        int k0 = s * 16 + (t & 3) * 2 + j2 * 8;
        g_wtb_u[idx] = pack_pair(Wf[n * 128 + k0], Wf[n * 128 + k0 + 1]);
    } else {                               // combined gate bias
        int i = idx - WTB_TOTAL;
        g_gb[i] = bih[i] + bhh[i];
    }
}

// ---- persistent RITS scan: 128 CTAs x 8 rows, 1024 threads (32 warps), 5 barriers/step ----
// fp16 activation shadow actH[8][PH]: per row r:
//   [0:128) c_c | [128:256) m | [256:512) hd | [512:640) gx | [640:768) m copy | [768:896) dsa | [896:1024) x_c
#define PH 1032
__global__ void __launch_bounds__(NTHR, 1) rits_kernel(
    const float* __restrict__ values, const int* __restrict__ masks, const float* __restrict__ deltas,
    const float* __restrict__ bdh, const float* __restrict__ bdx,
    const float* __restrict__ bh,  const float* __restrict__ bf_,
    const float* __restrict__ bc,
    const float* __restrict__ Wo,  const float* __restrict__ bo,
    float* __restrict__ out)
{
    extern __shared__ float smem[];
    float* hs  = smem;            // [H*8]
    float* cs  = hs  + 2048;      // [H*8]
    float* xs  = cs  + 2048;      // [D*8]
    float* msa = xs  + 1024;      // [D*8]
    float* al  = msa + 1024;      // [D*8]  alpha
    __half* actH = (__half*)(al + 1024);  // [8][PH]

    const int j = threadIdx.x;
    const int w = j >> 5, tl = j & 31;
    const int rr = tl >> 2, c4 = tl & 3;
    const int rowbase = blockIdx.x * NROWS;
    float* out_imp = out + BB * CCLS;

    for (int i = j; i < 4096; i += NTHR) { hs[i] = 0.f; }  // hs+cs contiguous zero

    // input prefetch (1 elem/thread)
    float pv, pm, pd;
    {
        const int r = j >> 7, k = j & 127;
        const int g = rowbase * (TT * DD) + r * (TT * DD) + k;
        pv = values[g]; pm = (float)masks[g]; pd = deltas[g];
    }
    __syncthreads();

    const int r1 = j >> 7, k1 = j & 127;          // phase-1 mapping
    for (int t = 0; t < TT; ++t) {
        // ---- phase 1: commit prefetched x, m, d ----
        {
            int si = k1 * 8 + r1;
            xs[si] = pv; msa[si] = pm;
            __half mh = __float2half(pm);
            actH[r1 * PH + 128 + k1] = mh;
            actH[r1 * PH + 640 + k1] = mh;
            actH[r1 * PH + 768 + k1] = __float2half(pd);
        }
        __syncthreads();                           // B1

        // issue next step's input loads
        if (t + 1 < TT) {
            int g = rowbase * (TT * DD) + r1 * (TT * DD) + (t + 1) * DD + k1;
            pv = values[g]; pm = (float)masks[g]; pd = deltas[g];
        }

        // ---- phase 2 (G1): gamma_h | gamma_x; 48 tiles: T=w (all), T=32+w (w<16) ----
        {
            const __half* arow = actH + rr * PH + 768 + c4 * 2;
            const uint2* fb = (const uint2*)(g_wtb_u + SMG1);
            float acc0 = 0.f, acc1 = 0.f, accB0 = 0.f, accB1 = 0.f;
            float d2 = 0.f, d3 = 0.f;
            const int T1 = w;
            const int cw1 = T1 / 3, cu1 = T1 - cw1 * 3;
            const int T2 = 32 + w;
            const int cw2 = T2 / 3, cu2 = T2 - cw2 * 3;
            const bool two = (w < 16);
            #pragma unroll 2
            for (int s = 0; s < 8; ++s) {
                uint32_t a0 = *(const uint32_t*)(arow + s * 16);
                uint32_t a2 = *(const uint32_t*)(arow + s * 16 + 8);
                uint2 b0 = fb[((cw1 * 8 + s) * 3 + cu1) * 32 + tl];
                mma1(acc0, acc1, d2, d3, a0, a2, b0.x, b0.y);
                if (two) {
                    uint2 b1 = fb[((cw2 * 8 + s) * 3 + cu2) * 32 + tl];
                    mma1(accB0, accB1, d2, d3, a0, a2, b1.x, b1.y);
                }
            }
            {
                int n0 = T1 * 8 + c4 * 2;
                #pragma unroll
                for (int c = 0; c < 2; ++c) {
                    int n = n0 + c;
                    float v = (c == 0) ? acc0 : acc1;
                    float gam = __expf(-fmaxf(v + bdh[n], 0.f));
                    float hv = hs[n * 8 + rr] * gam;
                    actH[rr * PH + 256 + n] = __float2half(hv);
                }
            }
            if (two) {
                int n0 = T2 * 8 - 256 + c4 * 2;
                #pragma unroll
                for (int c = 0; c < 2; ++c) {
                    int n2 = n0 + c;
                    float v = (c == 0) ? accB0 : accB1;
                    float gxv = __expf(-fmaxf(v + bdx[n2], 0.f));
                    actH[rr * PH + 512 + n2] = __float2half(gxv);
                }
            }
        }
        __syncthreads();                           // B2

        // ---- phase 3 (G2): x_h + x_c (warps 0-15) | alpha (warps 16-31) ----
        float xh0 = 0.f, xh1 = 0.f;                // live across B3 into phase 4
        {
            const bool isA = (w < 16);
            const int T = isA ? w : (w - 16);
            const int wl = T >> 1, uu = T & 1;
            const __half* arow = actH + rr * PH + (isA ? 256 : 512) + c4 * 2;
            const uint2* fb = (const uint2*)(g_wtb_u + (isA ? SMG2A : SMG2B));
            float acc0 = 0.f, acc1 = 0.f, d2 = 0.f, d3 = 0.f;
            #pragma unroll 4
            for (int s = 0; s < 16; ++s) {
                uint32_t a0 = *(const uint32_t*)(arow + s * 16);
                uint32_t a2 = *(const uint32_t*)(arow + s * 16 + 8);
                uint2 b0 = fb[((wl * 16 + s) * 2 + uu) * 32 + tl];
                mma1(acc0, acc1, d2, d3, a0, a2, b0.x, b0.y);
            }
            int n0 = T * 8 + c4 * 2;
            if (isA) {
                xh0 = acc0 + bh[n0];
                xh1 = acc1 + bh[n0 + 1];
                // fused x_c = m*x + (1-m)*x_h  -> fp16 shadow
                float m0 = msa[n0 * 8 + rr],       x0 = xs[n0 * 8 + rr];
                float m1 = msa[(n0 + 1) * 8 + rr], x1 = xs[(n0 + 1) * 8 + rr];
                actH[rr * PH + 896 + n0]     = __float2half(m0 * x0 + (1.f - m0) * xh0);
                actH[rr * PH + 896 + n0 + 1] = __float2half(m1 * x1 + (1.f - m1) * xh1);
            } else {
                al[n0 * 8 + rr]       = acc0 + bc[n0];
                al[(n0 + 1) * 8 + rr] = acc1 + bc[n0 + 1];
            }
        }
        __syncthreads();                           // B3

        // ---- phase 4 (G3): z_h + c_h + c_c + imputation (warps 0-15) ----
        if (w < 16) {
            float acc0 = 0.f, acc1 = 0.f, d2 = 0.f, d3 = 0.f;
            const __half* arow = actH + rr * PH + 896 + c4 * 2;
            const uint2* fb = (const uint2*)(g_wtb_u + SMG3);
            #pragma unroll 2
            for (int s = 0; s < 8; ++s) {
                uint32_t a0 = *(const uint32_t*)(arow + s * 16);
                uint32_t a2 = *(const uint32_t*)(arow + s * 16 + 8);
                uint2 b0 = fb[(w * 8 + s) * 32 + tl];
                mma1(acc0, acc1, d2, d3, a0, a2, b0.x, b0.y);
            }
            int n0 = w * 8 + c4 * 2;
            const int gbase = rowbase * (TT * DD) + rr * (TT * DD) + t * DD;
            #pragma unroll
            for (int c = 0; c < 2; ++c) {
                int n = n0 + c;
                float zv = ((c == 0) ? acc0 : acc1) + bf_[n];
                float xhv = (c == 0) ? xh0 : xh1;
                float a = al[n * 8 + rr];
                float mv = msa[n * 8 + rr], xv = xs[n * 8 + rr];
                float ch = a * zv + (1.f - a) * xhv;
                float cc = mv * xv + (1.f - mv) * ch;
                actH[rr * PH + n] = __float2half(cc);
                out_imp[gbase + n] = cc;
            }
        }
        __syncthreads();                           // B4

        // ---- phase 5 (gates + LSTM fused): warp w owns h-cols [w*8, w*8+8) ----
        {
            float acc[4][2];                       // u = gate (i,f,g,o)
            #pragma unroll
            for (int u = 0; u < 4; ++u) { acc[u][0] = 0.f; acc[u][1] = 0.f; }
            float d2 = 0.f, d3 = 0.f;
            const uint4* fragbase = (const uint4*)g_wtb_u + (size_t)w * 2048 + tl;
            const __half* arow = actH + rr * PH + c4 * 2;
            #pragma unroll 4
            for (int s = 0; s < 32; ++s) {
                uint32_t a0 = *(const uint32_t*)(arow + s * 16);
                uint32_t a2 = *(const uint32_t*)(arow + s * 16 + 8);
                const uint4* wp = fragbase + s * 64;
                uint4 q0 = wp[0], q1 = wp[32];
                mma1(acc[0][0], acc[0][1], d2, d3, a0, a2, q0.x, q0.y);
                mma1(acc[1][0], acc[1][1], d2, d3, a0, a2, q0.z, q0.w);
                mma1(acc[2][0], acc[2][1], d2, d3, a0, a2, q1.x, q1.y);
                mma1(acc[3][0], acc[3][1], d2, d3, a0, a2, q1.z, q1.w);
            }
            int n0 = w * 8 + c4 * 2;
            #pragma unroll
            for (int c = 0; c < 2; ++c) {
                int n = n0 + c;
                float ig = sigf(acc[0][c] + g_gb[n]);
                float fg = sigf(acc[1][c] + g_gb[256 + n]);
                float gg = tanh_fast(acc[2][c] + g_gb[512 + n]);
                float og = sigf(acc[3][c] + g_gb[768 + n]);
                float cn = fg * cs[n * 8 + rr] + ig * gg;
                cs[n * 8 + rr] = cn;
                hs[n * 8 + rr] = og * tanh_fast(cn);
            }
        }
        __syncthreads();                           // B5
    }

    // ---- final: y_h = h@Wo.T + bo ----
    if (j < NROWS * CCLS) {
        int r = j >> 1, cl = j & 1;
        float acc = bo[cl];
        #pragma unroll 8
        for (int k = 0; k < HH; ++k) acc += hs[k * 8 + r] * Wo[cl * HH + k];
        out[(rowbase + r) * CCLS + cl] = acc;
    }
}

extern "C" void kernel_launch(void* const* d_in, const int* in_sizes, int n_in,
                              void* d_out, int out_size) {
    const float* values = (const float*)d_in[0];
    const int*   masks  = (const int*)  d_in[1];
    const float* deltas = (const float*)d_in[2];
    const float* Wdh = (const float*)d_in[3];
    const float* bdh = (const float*)d_in[4];
    const float* Wdx = (const float*)d_in[5];
    const float* bdx = (const float*)d_in[6];
    const float* Wh  = (const float*)d_in[7];
    const float* bh  = (const float*)d_in[8];
    const float* Wf  = (const float*)d_in[9];
    const float* bf_ = (const float*)d_in[10];
    const float* Wc  = (const float*)d_in[11];
    const float* bc  = (const float*)d_in[12];
    const float* Wih = (const float*)d_in[13];
    const float* bih = (const float*)d_in[14];
    const float* Whh = (const float*)d_in[15];
    const float* bhh = (const float*)d_in[16];
    const float* Wo  = (const float*)d_in[17];
    const float* bo  = (const float*)d_in[18];
    float* out = (float*)d_out;

    prep_kernel<<<(PREP_TOTAL + 255) / 256, 256>>>(Wdh, Wdx, Wh, Wf, Wc, Wih, Whh, bih, bhh);

    // smem: 7168 floats (28672 B) + actH 8*1032 halves (16512 B) = 45184 B
    size_t smem_bytes = 7168 * sizeof(float) + 8 * PH * sizeof(__half);
    cudaFuncSetAttribute(rits_kernel, cudaFuncAttributeMaxDynamicSharedMemorySize,
                         (int)smem_bytes);
    rits_kernel<<<NCTA, NTHR, smem_bytes>>>(values, masks, deltas,
                                            bdh, bdx, bh, bf_, bc,
                                            Wo, bo, out);
}

// round 11
// speedup vs baseline: 1.6991x; 1.1024x over previous
#include <cuda_runtime.h>
#include <cuda_bf16.h>
#include <cuda_fp16.h>
#include <cstdint>

// Problem dims
#define BB 1024
#define TT 512
#define DD 128
#define HH 256
#define CCLS 2
#define NROWS 8
#define NCTA (BB / NROWS)   // 128 CTAs
#define NTHR 1024

// ---- fragment-packed fp16 weights (device global; no allocations allowed) ----
// Gates [0, 262144) u32, gate-fused layout (32 warps):
//   i = (((w*32 + s)*2 + v)*128 + t*4 + e,  u = v*2 + (e>>1), j2 = e&1
//   warp w owns h-cols [w*8, w*8+8); tile u = gate index (0=i,1=f,2=g,3=o)
//   k0 = s*16 + (t&3)*2 + j2*8,  N = u*256 + w*8 + (t>>2)
//   val = half2(W[k0][N], W[k0+1][N]),  W[k][N] = k<256 ? Wih[N][k] : Whh[N][k-256]
// Small GEMM fragments (uint2 per (lane,tile,step)):
//   G1 (gamma_h|gamma_x: K=128, N=384):  i=((cw*8+s)*3+cu)*64 + t*2 + j2, T=cw*3+cu
//   G2a (x_h: K=256,N=128):  i=((wl*16+s)*2+uu)*64 + t*2 + j2, T=wl*2+uu
//   G2b (alpha: K=256,N=128): same layout, separate base
//   G3 (z_h: K=128,N=128): i=(T*8+s)*64 + t*2 + j2
#define SMG1  262144
#define SMG2A 286720
#define SMG2B 303104
#define SMG3  319488
#define WTB_TOTAL 327680
__device__ uint32_t g_wtb_u[WTB_TOTAL];
// Combined gate bias bih+bhh
__device__ float g_gb[4 * HH];

__device__ __forceinline__ float sigf(float x) { return 1.f / (1.f + __expf(-x)); }
__device__ __forceinline__ float tanh_fast(float x) { return 2.f / (1.f + __expf(-2.f * x)) - 1.f; }

// m16n8k16 HMMA; A rows 8-15 zero, c2/c3 discarded.
__device__ __forceinline__ void mma1(float& c0, float& c1, float& c2, float& c3,
                                     uint32_t a0, uint32_t a2, uint32_t b0, uint32_t b1) {
    asm volatile(
        "mma.sync.aligned.m16n8k16.row.col.f32.f16.f16.f32 "
        "{%0,%1,%2,%3}, {%4,%5,%6,%7}, {%8,%9}, {%0,%1,%2,%3};"
        : "+f"(c0), "+f"(c1), "+f"(c2), "+f"(c3)
        : "r"(a0), "r"(0u), "r"(a2), "r"(0u), "r"(b0), "r"(b1));
}

// ldmatrix x4: loads a0(s), a2(s), a0(s+1), a2(s+1) for two consecutive k-steps.
__device__ __forceinline__ void ldsm4(uint32_t addr, uint32_t& r0, uint32_t& r1,
                                      uint32_t& r2, uint32_t& r3) {
    asm volatile("ldmatrix.sync.aligned.m8n8.x4.shared.b16 {%0,%1,%2,%3}, [%4];"
        : "=r"(r0), "=r"(r1), "=r"(r2), "=r"(r3) : "r"(addr));
}

__device__ __forceinline__ uint32_t pack_pair(float lo, float hi) {
    uint32_t l = __half_as_ushort(__float2half_rn(lo));
    uint32_t h = __half_as_ushort(__float2half_rn(hi));
    return l | (h << 16);
}

// ---- fused prologue: all fragment packing + bias combine, ONE launch ----
#define PREP_TOTAL (WTB_TOTAL + 1024)
__global__ void prep_kernel(const float* __restrict__ Wdh, const float* __restrict__ Wdx,
                            const float* __restrict__ Wh,  const float* __restrict__ Wf,
                            const float* __restrict__ Wc,  const float* __restrict__ Wih,
                            const float* __restrict__ Whh, const float* __restrict__ bih,
                            const float* __restrict__ bhh) {
    int idx = blockIdx.x * blockDim.x + threadIdx.x;
    if (idx >= PREP_TOTAL) return;
    if (idx < 262144) {                    // gates, gate-fused coalesced layout
        int e = idx & 3, t = (idx >> 2) & 31, v = (idx >> 7) & 1;
        int s = (idx >> 8) & 31, w = (idx >> 13) & 31;
        int u = v * 2 + (e >> 1), j2 = e & 1;
        int k0 = s * 16 + (t & 3) * 2 + j2 * 8;
        int N  = u * 256 + w * 8 + (t >> 2);
        float lo, hi;
        if (k0 < 256) { lo = Wih[N * 256 + k0];       hi = Wih[N * 256 + k0 + 1]; }
        else          { lo = Whh[N * 256 + k0 - 256]; hi = Whh[N * 256 + k0 - 255]; }
        g_wtb_u[idx] = pack_pair(lo, hi);
    } else if (idx < SMG2A) {              // G1
        int i = idx - SMG1;
        int j2 = i & 1, t = (i >> 1) & 31;
        int rest = i >> 6, uu = rest % 3, ws = rest / 3;
        int s = ws & 7, w = ws >> 3;
        int tile = w * 3 + uu;
        int n = tile * 8 + (t >> 2);
        int k0 = s * 16 + (t & 3) * 2 + j2 * 8;
        float lo, hi;
        if (n < 256) { lo = Wdh[n * 128 + k0]; hi = Wdh[n * 128 + k0 + 1]; }
        else { int n2 = n - 256; lo = Wdx[n2 * 128 + k0]; hi = Wdx[n2 * 128 + k0 + 1]; }
        g_wtb_u[idx] = pack_pair(lo, hi);
    } else if (idx < SMG2B) {              // G2a: Wh
        int i = idx - SMG2A;
        int j2 = i & 1, t = (i >> 1) & 31;
        int rest = i >> 6, uu = rest & 1, ws = rest >> 1;
        int s = ws & 15, w = ws >> 4;
        int n = (w * 2 + uu) * 8 + (t >> 2);
        int k0 = s * 16 + (t & 3) * 2 + j2 * 8;
        g_wtb_u[idx] = pack_pair(Wh[n * 256 + k0], Wh[n * 256 + k0 + 1]);
    } else if (idx < SMG3) {               // G2b: Wc (input = gx || m)
        int i = idx - SMG2B;
        int j2 = i & 1, t = (i >> 1) & 31;
        int rest = i >> 6, uu = rest & 1, ws = rest >> 1;
        int s = ws & 15, w = ws >> 4;
        int n = (w * 2 + uu) * 8 + (t >> 2);
        int k0 = s * 16 + (t & 3) * 2 + j2 * 8;
        g_wtb_u[idx] = pack_pair(Wc[n * 256 + k0], Wc[n * 256 + k0 + 1]);
    } else if (idx < WTB_TOTAL) {          // G3: Wf
        int i = idx - SMG3;
        int j2 = i & 1, t = (i >> 1) & 31;
        int rest = i >> 6, s = rest & 7, w = rest >> 3;
        int n = w * 8 + (t >> 2);
        int k0 = s * 16 + (t & 3) * 2 + j2 * 8;
        g_wtb_u[idx] = pack_pair(Wf[n * 128 + k0], Wf[n * 128 + k0 + 1]);
    } else {                               // combined gate bias
        int i = idx - WTB_TOTAL;
        g_gb[i] = bih[i] + bhh[i];
    }
}

// ---- persistent RITS scan: 128 CTAs x 8 rows, 1024 threads, 4 barriers/step ----
// fp16 shadow actH[8][PH] per row:
//   W0 [0:512) / W1 [512:1024): parity gates A-window = c_c(128)|m(128)|hd(256)
//   [1024:1152) gx | [1152:1280) m_copy | [1280:1408) dsa | [1408:1536) x_c
#define PH 1544   // row stride 3088 B -> 4-bank shift per row (conflict-free LDSM)
#define OFF_GX 1024
#define OFF_MC 1152
#define OFF_DS 1280
#define OFF_XC 1408
__global__ void __launch_bounds__(NTHR, 1) rits_kernel(
    const float* __restrict__ values, const int* __restrict__ masks, const float* __restrict__ deltas,
    const float* __restrict__ bdh, const float* __restrict__ bdx,
    const float* __restrict__ bh,  const float* __restrict__ bf_,
    const float* __restrict__ bc,
    const float* __restrict__ Wo,  const float* __restrict__ bo,
    float* __restrict__ out)
{
    extern __shared__ float smem[];
    float* hs  = smem;            // [H*8]
    float* cs  = hs  + 2048;      // [H*8]
    float* xs  = cs  + 2048;      // [D*8]
    float* msa = xs  + 1024;      // [D*8]
    float* al  = msa + 1024;      // [D*8]  alpha
    __half* actH = (__half*)(al + 1024);  // [8][PH]

    const int j = threadIdx.x;
    const int w = j >> 5, tl = j & 31;
    const int rr = tl >> 2, c4 = tl & 3;
    const int rowbase = blockIdx.x * NROWS;
    float* out_imp = out + BB * CCLS;

    // LDSM lane address base (bytes): row = tl&7, matrix idx = (tl>>3)&3 -> +0/8/16/24 halves
    const uint32_t actB = (uint32_t)__cvta_generic_to_shared(actH);
    const uint32_t lds_lane = ((tl & 7) * PH + ((tl >> 3) & 3) * 8) * 2;

    for (int i = j; i < 4096; i += NTHR) { hs[i] = 0.f; }  // hs+cs contiguous zero

    // input prefetch (1 elem/thread)
    const int r1 = j >> 7, k1 = j & 127;
    float pv, pm, pd;
    {
        int g = rowbase * (TT * DD) + r1 * (TT * DD) + k1;
        pv = values[g]; pm = (float)masks[g]; pd = deltas[g];
    }
    // commit step 0 (window 0)
    {
        int si = k1 * 8 + r1;
        xs[si] = pv; msa[si] = pm;
        __half mh = __float2half(pm);
        actH[r1 * PH + OFF_MC + k1] = mh;
        actH[r1 * PH + 128 + k1] = mh;                 // m_gates, window 0
        actH[r1 * PH + OFF_DS + k1] = __float2half(pd);
    }
    // prefetch step 1
    {
        int g = rowbase * (TT * DD) + r1 * (TT * DD) + DD + k1;
        pv = values[g]; pm = (float)masks[g]; pd = deltas[g];
    }
    __syncthreads();

    for (int t = 0; t < TT; ++t) {
        const int Wp = (t & 1) * 512;
        const int Wq = 512 - Wp;

        // ---- phase 2 (G1): gamma_h | gamma_x; tiles T=w (all), T=32+w (w<16) ----
        {
            const uint2* fb = (const uint2*)(g_wtb_u + SMG1);
            float acc0 = 0.f, acc1 = 0.f, accB0 = 0.f, accB1 = 0.f;
            float d2 = 0.f, d3 = 0.f;
            const int cw1 = w / 3, cu1 = w - cw1 * 3;
            const int T2 = 32 + w;
            const int cw2 = T2 / 3, cu2 = T2 - cw2 * 3;
            const bool two = (w < 16);
            const uint32_t abase = actB + lds_lane + OFF_DS * 2;
            #pragma unroll
            for (int s2 = 0; s2 < 4; ++s2) {
                uint32_t a0, a2, a0b, a2b;
                ldsm4(abase + s2 * 64, a0, a2, a0b, a2b);
                int s = s2 * 2;
                uint2 b0 = fb[((cw1 * 8 + s) * 3 + cu1) * 32 + tl];
                uint2 b1 = fb[((cw1 * 8 + s + 1) * 3 + cu1) * 32 + tl];
                mma1(acc0, acc1, d2, d3, a0, a2, b0.x, b0.y);
                mma1(acc0, acc1, d2, d3, a0b, a2b, b1.x, b1.y);
                if (two) {
                    uint2 c0 = fb[((cw2 * 8 + s) * 3 + cu2) * 32 + tl];
                    uint2 c1 = fb[((cw2 * 8 + s + 1) * 3 + cu2) * 32 + tl];
                    mma1(accB0, accB1, d2, d3, a0, a2, c0.x, c0.y);
                    mma1(accB0, accB1, d2, d3, a0b, a2b, c1.x, c1.y);
                }
            }
            {
                int n0 = w * 8 + c4 * 2;
                #pragma unroll
                for (int c = 0; c < 2; ++c) {
                    int n = n0 + c;
                    float v = (c == 0) ? acc0 : acc1;
                    float gam = __expf(-fmaxf(v + bdh[n], 0.f));
                    float hv = hs[n * 8 + rr] * gam;
                    actH[rr * PH + Wp + 256 + n] = __float2half(hv);
                }
            }
            if (two) {
                int n0 = T2 * 8 - 256 + c4 * 2;
                #pragma unroll
                for (int c = 0; c < 2; ++c) {
                    int n2 = n0 + c;
                    float v = (c == 0) ? accB0 : accB1;
                    float gxv = __expf(-fmaxf(v + bdx[n2], 0.f));
                    actH[rr * PH + OFF_GX + n2] = __float2half(gxv);
                }
            }
        }
        __syncthreads();                           // B2

        // ---- phase 3 (G2): x_h + x_c (warps 0-15) | alpha (warps 16-31) ----
        float xh0 = 0.f, xh1 = 0.f;                // live across B3 into phase 4
        {
            const bool isA = (w < 16);
            const int T = isA ? w : (w - 16);
            const int wl = T >> 1, uu = T & 1;
            const uint32_t abase = actB + lds_lane
                                 + (isA ? (Wp + 256) : OFF_GX) * 2;
            const uint2* fb = (const uint2*)(g_wtb_u + (isA ? SMG2A : SMG2B));
            float acc0 = 0.f, acc1 = 0.f, d2 = 0.f, d3 = 0.f;
            #pragma unroll
            for (int s2 = 0; s2 < 8; ++s2) {
                uint32_t a0, a2, a0b, a2b;
                ldsm4(abase + s2 * 64, a0, a2, a0b, a2b);
                int s = s2 * 2;
                uint2 b0 = fb[((wl * 16 + s) * 2 + uu) * 32 + tl];
                uint2 b1 = fb[((wl * 16 + s + 1) * 2 + uu) * 32 + tl];
                mma1(acc0, acc1, d2, d3, a0, a2, b0.x, b0.y);
                mma1(acc0, acc1, d2, d3, a0b, a2b, b1.x, b1.y);
            }
            int n0 = T * 8 + c4 * 2;
            if (isA) {
                xh0 = acc0 + bh[n0];
                xh1 = acc1 + bh[n0 + 1];
                float m0 = msa[n0 * 8 + rr],       x0 = xs[n0 * 8 + rr];
                float m1 = msa[(n0 + 1) * 8 + rr], x1 = xs[(n0 + 1) * 8 + rr];
                actH[rr * PH + OFF_XC + n0]     = __float2half(m0 * x0 + (1.f - m0) * xh0);
                actH[rr * PH + OFF_XC + n0 + 1] = __float2half(m1 * x1 + (1.f - m1) * xh1);
            } else {
                al[n0 * 8 + rr]       = acc0 + bc[n0];
                al[(n0 + 1) * 8 + rr] = acc1 + bc[n0 + 1];
            }
        }
        __syncthreads();                           // B3

        // ---- phase 4 (G3): z_h + c_h + c_c + imputation (warps 0-15) ----
        if (w < 16) {
            float acc0 = 0.f, acc1 = 0.f, d2 = 0.f, d3 = 0.f;
            const uint32_t abase = actB + lds_lane + OFF_XC * 2;
            const uint2* fb = (const uint2*)(g_wtb_u + SMG3);
            #pragma unroll
            for (int s2 = 0; s2 < 4; ++s2) {
                uint32_t a0, a2, a0b, a2b;
                ldsm4(abase + s2 * 64, a0, a2, a0b, a2b);
                int s = s2 * 2;
                uint2 b0 = fb[(w * 8 + s) * 32 + tl];
                uint2 b1 = fb[(w * 8 + s + 1) * 32 + tl];
                mma1(acc0, acc1, d2, d3, a0, a2, b0.x, b0.y);
                mma1(acc0, acc1, d2, d3, a0b, a2b, b1.x, b1.y);
            }
            int n0 = w * 8 + c4 * 2;
            const int gbase = rowbase * (TT * DD) + rr * (TT * DD) + t * DD;
            float cc2[2];
            #pragma unroll
            for (int c = 0; c < 2; ++c) {
                int n = n0 + c;
                float zv = ((c == 0) ? acc0 : acc1) + bf_[n];
                float xhv = (c == 0) ? xh0 : xh1;
                float a = al[n * 8 + rr];
                float mv = msa[n * 8 + rr], xv = xs[n * 8 + rr];
                float ch = a * zv + (1.f - a) * xhv;
                float cc = mv * xv + (1.f - mv) * ch;
                actH[rr * PH + Wp + n] = __float2half(cc);
                cc2[c] = cc;
            }
            *(float2*)&out_imp[gbase + n0] = make_float2(cc2[0], cc2[1]);
        }
        __syncthreads();                           // B4

        // ---- phase 5: commit t+1 inputs, gates MMA, fused LSTM update ----
        {
            // head: commit step t+1 into parity window Wq + side regions
            if (t + 1 < TT) {
                int si = k1 * 8 + r1;
                xs[si] = pv; msa[si] = pm;
                __half mh = __float2half(pm);
                actH[r1 * PH + OFF_MC + k1] = mh;
                actH[r1 * PH + Wq + 128 + k1] = mh;
                actH[r1 * PH + OFF_DS + k1] = __float2half(pd);
            }
            if (t + 2 < TT) {
                int g = rowbase * (TT * DD) + r1 * (TT * DD) + (t + 2) * DD + k1;
                pv = values[g]; pm = (float)masks[g]; pd = deltas[g];
            }

            float acc[4][2];                       // u = gate (i,f,g,o)
            #pragma unroll
            for (int u = 0; u < 4; ++u) { acc[u][0] = 0.f; acc[u][1] = 0.f; }
            float d2 = 0.f, d3 = 0.f;
            const uint4* fragbase = (const uint4*)g_wtb_u + (size_t)w * 2048 + tl;
            const uint32_t abase = actB + lds_lane + Wp * 2;
            #pragma unroll 4
            for (int s2 = 0; s2 < 16; ++s2) {
                uint32_t a0, a2, a0b, a2b;
                ldsm4(abase + s2 * 64, a0, a2, a0b, a2b);
                int s = s2 * 2;
                const uint4* wp0 = fragbase + s * 64;
                uint4 q0 = wp0[0], q1 = wp0[32];
                mma1(acc[0][0], acc[0][1], d2, d3, a0, a2, q0.x, q0.y);
                mma1(acc[1][0], acc[1][1], d2, d3, a0, a2, q0.z, q0.w);
                mma1(acc[2][0], acc[2][1], d2, d3, a0, a2, q1.x, q1.y);
                mma1(acc[3][0], acc[3][1], d2, d3, a0, a2, q1.z, q1.w);
                const uint4* wp1 = fragbase + (s + 1) * 64;
                uint4 q2 = wp1[0], q3 = wp1[32];
                mma1(acc[0][0], acc[0][1], d2, d3, a0b, a2b, q2.x, q2.y);
                mma1(acc[1][0], acc[1][1], d2, d3, a0b, a2b, q2.z, q2.w);
                mma1(acc[2][0], acc[2][1], d2, d3, a0b, a2b, q3.x, q3.y);
                mma1(acc[3][0], acc[3][1], d2, d3, a0b, a2b, q3.z, q3.w);
            }
            int n0 = w * 8 + c4 * 2;
            #pragma unroll
            for (int c = 0; c < 2; ++c) {
                int n = n0 + c;
                float ig = sigf(acc[0][c] + g_gb[n]);
                float fg = sigf(acc[1][c] + g_gb[256 + n]);
                float gg = tanh_fast(acc[2][c] + g_gb[512 + n]);
                float og = sigf(acc[3][c] + g_gb[768 + n]);
                float cn = fg * cs[n * 8 + rr] + ig * gg;
                cs[n * 8 + rr] = cn;
                hs[n * 8 + rr] = og * tanh_fast(cn);
            }
        }
        __syncthreads();                           // B5
    }

    // ---- final: y_h = h@Wo.T + bo ----
    if (j < NROWS * CCLS) {
        int r = j >> 1, cl = j & 1;
        float acc = bo[cl];
        #pragma unroll 8
        for (int k = 0; k < HH; ++k) acc += hs[k * 8 + r] * Wo[cl * HH + k];
        out[(rowbase + r) * CCLS + cl] = acc;
    }
}

extern "C" void kernel_launch(void* const* d_in, const int* in_sizes, int n_in,
                              void* d_out, int out_size) {
    const float* values = (const float*)d_in[0];
    const int*   masks  = (const int*)  d_in[1];
    const float* deltas = (const float*)d_in[2];
    const float* Wdh = (const float*)d_in[3];
    const float* bdh = (const float*)d_in[4];
    const float* Wdx = (const float*)d_in[5];
    const float* bdx = (const float*)d_in[6];
    const float* Wh  = (const float*)d_in[7];
    const float* bh  = (const float*)d_in[8];
    const float* Wf  = (const float*)d_in[9];
    const float* bf_ = (const float*)d_in[10];
    const float* Wc  = (const float*)d_in[11];
    const float* bc  = (const float*)d_in[12];
    const float* Wih = (const float*)d_in[13];
    const float* bih = (const float*)d_in[14];
    const float* Whh = (const float*)d_in[15];
    const float* bhh = (const float*)d_in[16];
    const float* Wo  = (const float*)d_in[17];
    const float* bo  = (const float*)d_in[18];
    float* out = (float*)d_out;

    prep_kernel<<<(PREP_TOTAL + 255) / 256, 256>>>(Wdh, Wdx, Wh, Wf, Wc, Wih, Whh, bih, bhh);

    // smem: 7168 floats (28672 B) + actH 8*1544 halves (24704 B) = 53376 B
    size_t smem_bytes = 7168 * sizeof(float) + 8 * PH * sizeof(__half);
    cudaFuncSetAttribute(rits_kernel, cudaFuncAttributeMaxDynamicSharedMemorySize,
                         (int)smem_bytes);
    rits_kernel<<<NCTA, NTHR, smem_bytes>>>(values, masks, deltas,
                                            bdh, bdx, bh, bf_, bc,
                                            Wo, bo, out);
}

// round 12
// speedup vs baseline: 1.8326x; 1.0786x over previous
#include <cuda_runtime.h>
#include <cuda_bf16.h>
#include <cuda_fp16.h>
#include <cstdint>

// Problem dims
#define BB 1024
#define TT 512
#define DD 128
#define HH 256
#define CCLS 2
#define NROWS 8
#define NCTA (BB / NROWS)   // 128 CTAs
#define NTHR 1024

// ---- fragment-packed fp16 weights (device global; no allocations allowed) ----
// Gates [0, 262144) u32, gate-fused layout (32 warps):
//   i = (((w*32 + s)*2 + v)*128 + t*4 + e,  u = v*2 + (e>>1), j2 = e&1
//   warp w owns h-cols [w*8, w*8+8); tile u = gate index (0=i,1=f,2=g,3=o)
//   k0 = s*16 + (t&3)*2 + j2*8,  N = u*256 + w*8 + (t>>2)
//   val = half2(W[k0][N], W[k0+1][N]),  W[k][N] = k<256 ? Wih[N][k] : Whh[N][k-256]
//   NOTE: i/f/o gate weights (u != 2) are pre-scaled by 0.5 (exact in fp16) so that
//   sigmoid(x) = 0.5*tanh.approx(x/2) + 0.5 needs no runtime halving.
// Small GEMM fragments (uint2 per (lane,tile,step)):
//   G1 (gamma_h|gamma_x: K=128, N=384):  i=((cw*8+s)*3+cu)*64 + t*2 + j2, T=cw*3+cu
//   G2a (x_h: K=256,N=128):  i=((wl*16+s)*2+uu)*64 + t*2 + j2, T=wl*2+uu
//   G2b (alpha: K=256,N=128): same layout, separate base
//   G3 (z_h: K=128,N=128): i=(T*8+s)*64 + t*2 + j2
#define SMG1  262144
#define SMG2A 286720
#define SMG2B 303104
#define SMG3  319488
#define WTB_TOTAL 327680
__device__ uint32_t g_wtb_u[WTB_TOTAL];
// Combined gate bias bih+bhh (i/f/o pre-scaled by 0.5)
__device__ float g_gb[4 * HH];

// 1-MUFU tanh (sm_75+): max rel err ~2^-11
__device__ __forceinline__ float tanha(float x) {
    float y; asm("tanh.approx.f32 %0, %1;" : "=f"(y) : "f"(x)); return y;
}

// m16n8k16 HMMA; A rows 8-15 zero, c2/c3 discarded.
__device__ __forceinline__ void mma1(float& c0, float& c1, float& c2, float& c3,
                                     uint32_t a0, uint32_t a2, uint32_t b0, uint32_t b1) {
    asm volatile(
        "mma.sync.aligned.m16n8k16.row.col.f32.f16.f16.f32 "
        "{%0,%1,%2,%3}, {%4,%5,%6,%7}, {%8,%9}, {%0,%1,%2,%3};"
        : "+f"(c0), "+f"(c1), "+f"(c2), "+f"(c3)
        : "r"(a0), "r"(0u), "r"(a2), "r"(0u), "r"(b0), "r"(b1));
}

// ldmatrix x4: loads a0(s), a2(s), a0(s+1), a2(s+1) for two consecutive k-steps.
__device__ __forceinline__ void ldsm4(uint32_t addr, uint32_t& r0, uint32_t& r1,
                                      uint32_t& r2, uint32_t& r3) {
    asm volatile("ldmatrix.sync.aligned.m8n8.x4.shared.b16 {%0,%1,%2,%3}, [%4];"
        : "=r"(r0), "=r"(r1), "=r"(r2), "=r"(r3) : "r"(addr));
}

__device__ __forceinline__ uint32_t pack_pair(float lo, float hi) {
    uint32_t l = __half_as_ushort(__float2half_rn(lo));
    uint32_t h = __half_as_ushort(__float2half_rn(hi));
    return l | (h << 16);
}

// ---- fused prologue: all fragment packing + bias combine, ONE launch ----
#define PREP_TOTAL (WTB_TOTAL + 1024)
__global__ void prep_kernel(const float* __restrict__ Wdh, const float* __restrict__ Wdx,
                            const float* __restrict__ Wh,  const float* __restrict__ Wf,
                            const float* __restrict__ Wc,  const float* __restrict__ Wih,
                            const float* __restrict__ Whh, const float* __restrict__ bih,
                            const float* __restrict__ bhh) {
    int idx = blockIdx.x * blockDim.x + threadIdx.x;
    if (idx >= PREP_TOTAL) return;
    if (idx < 262144) {                    // gates, gate-fused coalesced layout
        int e = idx & 3, t = (idx >> 2) & 31, v = (idx >> 7) & 1;
        int s = (idx >> 8) & 31, w = (idx >> 13) & 31;
        int u = v * 2 + (e >> 1), j2 = e & 1;
        int k0 = s * 16 + (t & 3) * 2 + j2 * 8;
        int N  = u * 256 + w * 8 + (t >> 2);
        float lo, hi;
        if (k0 < 256) { lo = Wih[N * 256 + k0];       hi = Wih[N * 256 + k0 + 1]; }
        else          { lo = Whh[N * 256 + k0 - 256]; hi = Whh[N * 256 + k0 - 255]; }
        if (u != 2) { lo *= 0.5f; hi *= 0.5f; }     // i/f/o: fold sigmoid x/2
        g_wtb_u[idx] = pack_pair(lo, hi);
    } else if (idx < SMG2A) {              // G1
        int i = idx - SMG1;
        int j2 = i & 1, t = (i >> 1) & 31;
        int rest = i >> 6, uu = rest % 3, ws = rest / 3;
        int s = ws & 7, w = ws >> 3;
        int tile = w * 3 + uu;
        int n = tile * 8 + (t >> 2);
        int k0 = s * 16 + (t & 3) * 2 + j2 * 8;
        float lo, hi;
        if (n < 256) { lo = Wdh[n * 128 + k0]; hi = Wdh[n * 128 + k0 + 1]; }
        else { int n2 = n - 256; lo = Wdx[n2 * 128 + k0]; hi = Wdx[n2 * 128 + k0 + 1]; }
        g_wtb_u[idx] = pack_pair(lo, hi);
    } else if (idx < SMG2B) {              // G2a: Wh
        int i = idx - SMG2A;
        int j2 = i & 1, t = (i >> 1) & 31;
        int rest = i >> 6, uu = rest & 1, ws = rest >> 1;
        int s = ws & 15, w = ws >> 4;
        int n = (w * 2 + uu) * 8 + (t >> 2);
        int k0 = s * 16 + (t & 3) * 2 + j2 * 8;
        g_wtb_u[idx] = pack_pair(Wh[n * 256 + k0], Wh[n * 256 + k0 + 1]);
    } else if (idx < SMG3) {               // G2b: Wc (input = gx || m)
        int i = idx - SMG2B;
        int j2 = i & 1, t = (i >> 1) & 31;
        int rest = i >> 6, uu = rest & 1, ws = rest >> 1;
        int s = ws & 15, w = ws >> 4;
        int n = (w * 2 + uu) * 8 + (t >> 2);
        int k0 = s * 16 + (t & 3) * 2 + j2 * 8;
        g_wtb_u[idx] = pack_pair(Wc[n * 256 + k0], Wc[n * 256 + k0 + 1]);
    } else if (idx < WTB_TOTAL) {          // G3: Wf
        int i = idx - SMG3;
        int j2 = i & 1, t = (i >> 1) & 31;
        int rest = i >> 6, s = rest & 7, w = rest >> 3;
        int n = w * 8 + (t >> 2);
        int k0 = s * 16 + (t & 3) * 2 + j2 * 8;
        g_wtb_u[idx] = pack_pair(Wf[n * 128 + k0], Wf[n * 128 + k0 + 1]);
    } else {                               // combined gate bias (i/f/o halved)
        int i = idx - WTB_TOTAL;
        float b = bih[i] + bhh[i];
        int gate = i >> 8;                 // 0=i,1=f,2=g,3=o
        if (gate != 2) b *= 0.5f;
        g_gb[i] = b;
    }
}

// ---- persistent RITS scan: 128 CTAs x 8 rows, 1024 threads, 4 barriers/step ----
// fp16 shadow actH[8][PH] per row:
//   W0 [0:512) / W1 [512:1024): parity gates A-window = c_c(128)|m(128)|hd(256)
//   [1024:1152) gx | [1152:1280) m_copy | [1280:1408) dsa | [1408:1536) x_c
#define PH 1544   // row stride 3088 B -> 4-bank shift per row (conflict-free LDSM)
#define OFF_GX 1024
#define OFF_MC 1152
#define OFF_DS 1280
#define OFF_XC 1408
__global__ void __launch_bounds__(NTHR, 1) rits_kernel(
    const float* __restrict__ values, const int* __restrict__ masks, const float* __restrict__ deltas,
    const float* __restrict__ bdh, const float* __restrict__ bdx,
    const float* __restrict__ bh,  const float* __restrict__ bf_,
    const float* __restrict__ bc,
    const float* __restrict__ Wo,  const float* __restrict__ bo,
    float* __restrict__ out)
{
    extern __shared__ float smem[];
    float* hs  = smem;            // [H*8]
    float* xs  = hs  + 2048;      // [D*8]
    float* msa = xs  + 1024;      // [D*8]
    float* al  = msa + 1024;      // [D*8]  alpha
    __half* actH = (__half*)(al + 1024);  // [8][PH]

    const int j = threadIdx.x;
    const int w = j >> 5, tl = j & 31;
    const int rr = tl >> 2, c4 = tl & 3;
    const int rowbase = blockIdx.x * NROWS;
    float* out_imp = out + BB * CCLS;

    // LDSM lane address base (bytes): row = tl&7, matrix idx = (tl>>3)&3 -> +0/8/16/24 halves
    const uint32_t actB = (uint32_t)__cvta_generic_to_shared(actH);
    const uint32_t lds_lane = ((tl & 7) * PH + ((tl >> 3) & 3) * 8) * 2;

    for (int i = j; i < 2048; i += NTHR) { hs[i] = 0.f; }

    // cell state lives in registers: phase-5 epilogue thread owns (n0..n0+1, rr) forever
    float csr[2] = {0.f, 0.f};

    // input prefetch (1 elem/thread)
    const int r1 = j >> 7, k1 = j & 127;
    float pv, pm, pd;
    {
        int g = rowbase * (TT * DD) + r1 * (TT * DD) + k1;
        pv = values[g]; pm = (float)masks[g]; pd = deltas[g];
    }
    // commit step 0 (window 0)
    {
        int si = k1 * 8 + r1;
        xs[si] = pv; msa[si] = pm;
        __half mh = __float2half(pm);
        actH[r1 * PH + OFF_MC + k1] = mh;
        actH[r1 * PH + 128 + k1] = mh;                 // m_gates, window 0
        actH[r1 * PH + OFF_DS + k1] = __float2half(pd);
    }
    // prefetch step 1
    {
        int g = rowbase * (TT * DD) + r1 * (TT * DD) + DD + k1;
        pv = values[g]; pm = (float)masks[g]; pd = deltas[g];
    }
    __syncthreads();

    for (int t = 0; t < TT; ++t) {
        const int Wp = (t & 1) * 512;
        const int Wq = 512 - Wp;

        // ---- phase 2 (G1): gamma_h | gamma_x; tiles T=w (all), T=32+w (w<16) ----
        {
            const uint2* fb = (const uint2*)(g_wtb_u + SMG1);
            float acc0 = 0.f, acc1 = 0.f, accB0 = 0.f, accB1 = 0.f;
            float d2 = 0.f, d3 = 0.f;
            const int cw1 = w / 3, cu1 = w - cw1 * 3;
            const int T2 = 32 + w;
            const int cw2 = T2 / 3, cu2 = T2 - cw2 * 3;
            const bool two = (w < 16);
            const uint32_t abase = actB + lds_lane + OFF_DS * 2;
            #pragma unroll
            for (int s2 = 0; s2 < 4; ++s2) {
                uint32_t a0, a2, a0b, a2b;
                ldsm4(abase + s2 * 64, a0, a2, a0b, a2b);
                int s = s2 * 2;
                uint2 b0 = fb[((cw1 * 8 + s) * 3 + cu1) * 32 + tl];
                uint2 b1 = fb[((cw1 * 8 + s + 1) * 3 + cu1) * 32 + tl];
                mma1(acc0, acc1, d2, d3, a0, a2, b0.x, b0.y);
                mma1(acc0, acc1, d2, d3, a0b, a2b, b1.x, b1.y);
                if (two) {
                    uint2 c0 = fb[((cw2 * 8 + s) * 3 + cu2) * 32 + tl];
                    uint2 c1 = fb[((cw2 * 8 + s + 1) * 3 + cu2) * 32 + tl];
                    mma1(accB0, accB1, d2, d3, a0, a2, c0.x, c0.y);
                    mma1(accB0, accB1, d2, d3, a0b, a2b, c1.x, c1.y);
                }
            }
            {
                int n0 = w * 8 + c4 * 2;
                #pragma unroll
                for (int c = 0; c < 2; ++c) {
                    int n = n0 + c;
                    float v = (c == 0) ? acc0 : acc1;
                    float gam = __expf(-fmaxf(v + bdh[n], 0.f));
                    float hv = hs[n * 8 + rr] * gam;
                    actH[rr * PH + Wp + 256 + n] = __float2half(hv);
                }
            }
            if (two) {
                int n0 = T2 * 8 - 256 + c4 * 2;
                #pragma unroll
                for (int c = 0; c < 2; ++c) {
                    int n2 = n0 + c;
                    float v = (c == 0) ? accB0 : accB1;
                    float gxv = __expf(-fmaxf(v + bdx[n2], 0.f));
                    actH[rr * PH + OFF_GX + n2] = __float2half(gxv);
                }
            }
        }
        __syncthreads();                           // B2

        // ---- phase 3 (G2): x_h + x_c (warps 0-15) | alpha (warps 16-31) ----
        float xh0 = 0.f, xh1 = 0.f;                // live across B3 into phase 4
        {
            const bool isA = (w < 16);
            const int T = isA ? w : (w - 16);
            const int wl = T >> 1, uu = T & 1;
            const uint32_t abase = actB + lds_lane
                                 + (isA ? (Wp + 256) : OFF_GX) * 2;
            const uint2* fb = (const uint2*)(g_wtb_u + (isA ? SMG2A : SMG2B));
            float acc0 = 0.f, acc1 = 0.f, d2 = 0.f, d3 = 0.f;
            #pragma unroll
            for (int s2 = 0; s2 < 8; ++s2) {
                uint32_t a0, a2, a0b, a2b;
                ldsm4(abase + s2 * 64, a0, a2, a0b, a2b);
                int s = s2 * 2;
                uint2 b0 = fb[((wl * 16 + s) * 2 + uu) * 32 + tl];
                uint2 b1 = fb[((wl * 16 + s + 1) * 2 + uu) * 32 + tl];
                mma1(acc0, acc1, d2, d3, a0, a2, b0.x, b0.y);
                mma1(acc0, acc1, d2, d3, a0b, a2b, b1.x, b1.y);
            }
            int n0 = T * 8 + c4 * 2;
            if (isA) {
                xh0 = acc0 + bh[n0];
                xh1 = acc1 + bh[n0 + 1];
                float m0 = msa[n0 * 8 + rr],       x0 = xs[n0 * 8 + rr];
                float m1 = msa[(n0 + 1) * 8 + rr], x1 = xs[(n0 + 1) * 8 + rr];
                actH[rr * PH + OFF_XC + n0]     = __float2half(m0 * x0 + (1.f - m0) * xh0);
                actH[rr * PH + OFF_XC + n0 + 1] = __float2half(m1 * x1 + (1.f - m1) * xh1);
            } else {
                al[n0 * 8 + rr]       = acc0 + bc[n0];
                al[(n0 + 1) * 8 + rr] = acc1 + bc[n0 + 1];
            }
        }
        __syncthreads();                           // B3

        // ---- phase 4 (G3): z_h + c_h + c_c + imputation (warps 0-15) ----
        if (w < 16) {
            float acc0 = 0.f, acc1 = 0.f, d2 = 0.f, d3 = 0.f;
            const uint32_t abase = actB + lds_lane + OFF_XC * 2;
            const uint2* fb = (const uint2*)(g_wtb_u + SMG3);
            #pragma unroll
            for (int s2 = 0; s2 < 4; ++s2) {
                uint32_t a0, a2, a0b, a2b;
                ldsm4(abase + s2 * 64, a0, a2, a0b, a2b);
                int s = s2 * 2;
                uint2 b0 = fb[(w * 8 + s) * 32 + tl];
                uint2 b1 = fb[(w * 8 + s + 1) * 32 + tl];
                mma1(acc0, acc1, d2, d3, a0, a2, b0.x, b0.y);
                mma1(acc0, acc1, d2, d3, a0b, a2b, b1.x, b1.y);
            }
            int n0 = w * 8 + c4 * 2;
            const int gbase = rowbase * (TT * DD) + rr * (TT * DD) + t * DD;
            float cc2[2];
            #pragma unroll
            for (int c = 0; c < 2; ++c) {
                int n = n0 + c;
                float zv = ((c == 0) ? acc0 : acc1) + bf_[n];
                float xhv = (c == 0) ? xh0 : xh1;
                float a = al[n * 8 + rr];
                float mv = msa[n * 8 + rr], xv = xs[n * 8 + rr];
                float ch = a * zv + (1.f - a) * xhv;
                float cc = mv * xv + (1.f - mv) * ch;
                actH[rr * PH + Wp + n] = __float2half(cc);
                cc2[c] = cc;
            }
            *(float2*)&out_imp[gbase + n0] = make_float2(cc2[0], cc2[1]);
        }
        __syncthreads();                           // B4

        // ---- phase 5: commit t+1 inputs, gates MMA, fused LSTM update ----
        {
            // head: commit step t+1 into parity window Wq + side regions
            if (t + 1 < TT) {
                int si = k1 * 8 + r1;
                xs[si] = pv; msa[si] = pm;
                __half mh = __float2half(pm);
                actH[r1 * PH + OFF_MC + k1] = mh;
                actH[r1 * PH + Wq + 128 + k1] = mh;
                actH[r1 * PH + OFF_DS + k1] = __float2half(pd);
            }
            if (t + 2 < TT) {
                int g = rowbase * (TT * DD) + r1 * (TT * DD) + (t + 2) * DD + k1;
                pv = values[g]; pm = (float)masks[g]; pd = deltas[g];
            }

            float acc[4][2];                       // u = gate (i,f,g,o)
            #pragma unroll
            for (int u = 0; u < 4; ++u) { acc[u][0] = 0.f; acc[u][1] = 0.f; }
            float d2 = 0.f, d3 = 0.f;
            const uint4* fragbase = (const uint4*)g_wtb_u + (size_t)w * 2048 + tl;
            const uint32_t abase = actB + lds_lane + Wp * 2;
            #pragma unroll 4
            for (int s2 = 0; s2 < 16; ++s2) {
                uint32_t a0, a2, a0b, a2b;
                ldsm4(abase + s2 * 64, a0, a2, a0b, a2b);
                int s = s2 * 2;
                const uint4* wp0 = fragbase + s * 64;
                uint4 q0 = wp0[0], q1 = wp0[32];
                mma1(acc[0][0], acc[0][1], d2, d3, a0, a2, q0.x, q0.y);
                mma1(acc[1][0], acc[1][1], d2, d3, a0, a2, q0.z, q0.w);
                mma1(acc[2][0], acc[2][1], d2, d3, a0, a2, q1.x, q1.y);
                mma1(acc[3][0], acc[3][1], d2, d3, a0, a2, q1.z, q1.w);
                const uint4* wp1 = fragbase + (s + 1) * 64;
                uint4 q2 = wp1[0], q3 = wp1[32];
                mma1(acc[0][0], acc[0][1], d2, d3, a0b, a2b, q2.x, q2.y);
                mma1(acc[1][0], acc[1][1], d2, d3, a0b, a2b, q2.z, q2.w);
                mma1(acc[2][0], acc[2][1], d2, d3, a0b, a2b, q3.x, q3.y);
                mma1(acc[3][0], acc[3][1], d2, d3, a0b, a2b, q3.z, q3.w);
            }
            int n0 = w * 8 + c4 * 2;
            #pragma unroll
            for (int c = 0; c < 2; ++c) {
                int n = n0 + c;
                // i/f/o pre-activations are pre-halved (weights+bias); sig = 0.5*tanh+0.5
                float ig = fmaf(tanha(acc[0][c] + g_gb[n]),       0.5f, 0.5f);
                float fg = fmaf(tanha(acc[1][c] + g_gb[256 + n]), 0.5f, 0.5f);
                float gg = tanha(acc[2][c] + g_gb[512 + n]);
                float og = fmaf(tanha(acc[3][c] + g_gb[768 + n]), 0.5f, 0.5f);
                float cn = fg * csr[c] + ig * gg;
                csr[c] = cn;
                hs[n * 8 + rr] = og * tanha(cn);
            }
        }
        __syncthreads();                           // B5
    }

    // ---- final: y_h = h@Wo.T + bo ----
    if (j < NROWS * CCLS) {
        int r = j >> 1, cl = j & 1;
        float acc = bo[cl];
        #pragma unroll 8
        for (int k = 0; k < HH; ++k) acc += hs[k * 8 + r] * Wo[cl * HH + k];
        out[(rowbase + r) * CCLS + cl] = acc;
    }
}

extern "C" void kernel_launch(void* const* d_in, const int* in_sizes, int n_in,
                              void* d_out, int out_size) {
    const float* values = (const float*)d_in[0];
    const int*   masks  = (const int*)  d_in[1];
    const float* deltas = (const float*)d_in[2];
    const float* Wdh = (const float*)d_in[3];
    const float* bdh = (const float*)d_in[4];
    const float* Wdx = (const float*)d_in[5];
    const float* bdx = (const float*)d_in[6];
    const float* Wh  = (const float*)d_in[7];
    const float* bh  = (const float*)d_in[8];
    const float* Wf  = (const float*)d_in[9];
    const float* bf_ = (const float*)d_in[10];
    const float* Wc  = (const float*)d_in[11];
    const float* bc  = (const float*)d_in[12];
    const float* Wih = (const float*)d_in[13];
    const float* bih = (const float*)d_in[14];
    const float* Whh = (const float*)d_in[15];
    const float* bhh = (const float*)d_in[16];
    const float* Wo  = (const float*)d_in[17];
    const float* bo  = (const float*)d_in[18];
    float* out = (float*)d_out;

    prep_kernel<<<(PREP_TOTAL + 255) / 256, 256>>>(Wdh, Wdx, Wh, Wf, Wc, Wih, Whh, bih, bhh);

    // smem: 5120 floats (20480 B) + actH 8*1544 halves (24704 B) = 45184 B
    size_t smem_bytes = 5120 * sizeof(float) + 8 * PH * sizeof(__half);
    cudaFuncSetAttribute(rits_kernel, cudaFuncAttributeMaxDynamicSharedMemorySize,
                         (int)smem_bytes);
    rits_kernel<<<NCTA, NTHR, smem_bytes>>>(values, masks, deltas,
                                            bdh, bdx, bh, bf_, bc,
                                            Wo, bo, out);
}